// round 12
// baseline (speedup 1.0000x reference)
#include <cuda_runtime.h>
#include <cuda_bf16.h>
#include <cstdint>
#include <math.h>

typedef unsigned int u32;

// Problem dims
#define BB   8
#define TT   2048
#define DD   300
#define KK   10
#define LL   8921
#define TP   2057     // TT + KK - 1
#define LP   8960     // L padded to 35*256
#define OP2  384      // o padded to 3*128
#define DP   320      // d padded to 20*16
#define TPAD 2176     // t' padded to 17*128
#define ETR  2208     // embed rows: 9 halo + 2048 + tail zeros
#define SSTR 40       // smem row stride in bf16 (80B)

// conv stage layout (bytes): 128-row A hi/lo + 128-row B hi/lo
#define C_AL   10240
#define C_BH   20480
#define C_BL   30720
#define C_STG  40960

// attn stage layout (bytes): 256-row A hi/lo + 128-row B hi/lo
#define A_AL   20480
#define A_BH   40960
#define A_BL   51200
#define A_STG  61440

// Scratch (device globals, zero-initialized; padding regions never written)
__device__ __align__(16) __nv_bfloat16 g_Ehi[BB * ETR * DP];   // [b][9+tau][d]
__device__ __align__(16) __nv_bfloat16 g_Elo[BB * ETR * DP];
__device__ __align__(16) __nv_bfloat16 g_Whi[KK * OP2 * DP];   // [k][o][i]
__device__ __align__(16) __nv_bfloat16 g_Wlo[KK * OP2 * DP];
__device__ __align__(16) __nv_bfloat16 g_Uhi[LP * DP];         // [l][d]
__device__ __align__(16) __nv_bfloat16 g_Ulo[LP * DP];
__device__ __align__(16) __nv_bfloat16 g_Hthi[BB * TPAD * DP]; // [b][t][o]
__device__ __align__(16) __nv_bfloat16 g_Htlo[BB * TPAD * DP];

// ---------------------------------------------------------------------------
// PTX helpers
// ---------------------------------------------------------------------------
__device__ __forceinline__ u32 smem_u32(const void* p) {
    return (u32)__cvta_generic_to_shared(p);
}

__device__ __forceinline__ void ldsm4(u32* r, u32 addr) {
    asm volatile("ldmatrix.sync.aligned.m8n8.x4.shared.b16 {%0,%1,%2,%3}, [%4];"
                 : "=r"(r[0]), "=r"(r[1]), "=r"(r[2]), "=r"(r[3])
                 : "r"(addr));
}

__device__ __forceinline__ void mma16816(float* d, const u32* a, const u32* b) {
    asm volatile(
        "mma.sync.aligned.m16n8k16.row.col.f32.bf16.bf16.f32 "
        "{%0,%1,%2,%3}, {%4,%5,%6,%7}, {%8,%9}, {%0,%1,%2,%3};"
        : "+f"(d[0]), "+f"(d[1]), "+f"(d[2]), "+f"(d[3])
        : "r"(a[0]), "r"(a[1]), "r"(a[2]), "r"(a[3]), "r"(b[0]), "r"(b[1]));
}

__device__ __forceinline__ void cpa16(u32 dst, const void* src) {
    asm volatile("cp.async.cg.shared.global [%0], [%1], 16;" :: "r"(dst), "l"(src));
}
__device__ __forceinline__ void cpa_commit() {
    asm volatile("cp.async.commit_group;");
}
__device__ __forceinline__ void cpa_wait1() {
    asm volatile("cp.async.wait_group 1;");
}
__device__ __forceinline__ void cpa_wait0() {
    asm volatile("cp.async.wait_group 0;");
}

// ---------------------------------------------------------------------------
// Kernel 1: embedding gather + bf16 hi/lo split -> Ehi/Elo[b][9+tau][d]
// ---------------------------------------------------------------------------
__global__ void k_gather(const int* __restrict__ ids, const float* __restrict__ emb) {
    int idx = blockIdx.x * 256 + threadIdx.x;
    if (idx >= BB * TT * DD) { return; }
    int d = idx % DD;
    int tok = idx / DD;
    int b = tok / TT;
    int tau = tok - b * TT;
    int row = ids[tok];
    float v = emb[row * DD + d];
    __nv_bfloat16 h = __float2bfloat16(v);
    size_t o = ((size_t)b * ETR + 9 + tau) * DP + d;
    g_Ehi[o] = h;
    g_Elo[o] = __float2bfloat16(v - __bfloat162float(h));
}

// ---------------------------------------------------------------------------
// Kernel 2: conv_w (O,I,K) fp32 -> Whi/Wlo[k][o][i]
// ---------------------------------------------------------------------------
__global__ void k_wsplit(const float* __restrict__ w) {
    int idx = blockIdx.x * 256 + threadIdx.x;
    if (idx >= KK * DD * DD) { return; }
    int i = idx % DD;
    int rem = idx / DD;
    int o = rem % DD;
    int k = rem / DD;
    float v = w[(o * DD + i) * KK + k];
    __nv_bfloat16 h = __float2bfloat16(v);
    size_t dst = ((size_t)k * OP2 + o) * DP + i;
    g_Whi[dst] = h;
    g_Wlo[dst] = __float2bfloat16(v - __bfloat162float(h));
}

// ---------------------------------------------------------------------------
// Kernel 3: U fp32 [l][d] -> bf16 hi/lo split [l][DP]
// ---------------------------------------------------------------------------
__global__ void k_usplit(const float* __restrict__ U) {
    int idx = blockIdx.x * 256 + threadIdx.x;
    if (idx >= LL * DD) { return; }
    int l = idx / DD;
    int d = idx - l * DD;
    float u = U[idx];
    __nv_bfloat16 h = __float2bfloat16(u);
    g_Uhi[l * DP + d] = h;
    g_Ulo[l * DP + d] = __float2bfloat16(u - __bfloat162float(h));
}

// ---------------------------------------------------------------------------
// 64x64 warp-tile mma step: 16 ldsm + 96 mma per kc, hi/lo 3-pass
//   a rows: warp_m*64 (+mt*16); b rows: warp_n*64 (+j2*16)
// ---------------------------------------------------------------------------
__device__ __forceinline__ void mma_step64(u32 sb, u32 off_al, u32 off_bh, u32 off_bl,
                                           const u32* aoff, const u32* boff,
                                           float acc[4][8][4]) {
#pragma unroll
    for (int kc = 0; kc < 2; kc++) {
        u32 kb = (u32)(kc * 32);
        u32 ah[4][4];
        u32 al[4][4];
        u32 bh[4][4];
        u32 bl[4][4];

#pragma unroll
        for (int mt = 0; mt < 4; mt++) { ldsm4(ah[mt], sb + aoff[mt] + kb); }
#pragma unroll
        for (int j2 = 0; j2 < 4; j2++) { ldsm4(bh[j2], sb + off_bh + boff[j2] + kb); }

        // pass 1: hi*hi
#pragma unroll
        for (int mt = 0; mt < 4; mt++) {
#pragma unroll
            for (int j = 0; j < 8; j++) {
                mma16816(acc[mt][j], ah[mt], &bh[j >> 1][(j & 1) * 2]);
            }
        }

        // pass 2: lo*hi
#pragma unroll
        for (int mt = 0; mt < 4; mt++) { ldsm4(al[mt], sb + off_al + aoff[mt] + kb); }
#pragma unroll
        for (int mt = 0; mt < 4; mt++) {
#pragma unroll
            for (int j = 0; j < 8; j++) {
                mma16816(acc[mt][j], al[mt], &bh[j >> 1][(j & 1) * 2]);
            }
        }

        // pass 3: hi*lo
#pragma unroll
        for (int j2 = 0; j2 < 4; j2++) { ldsm4(bl[j2], sb + off_bl + boff[j2] + kb); }
#pragma unroll
        for (int mt = 0; mt < 4; mt++) {
#pragma unroll
            for (int j = 0; j < 8; j++) {
                mma16816(acc[mt][j], ah[mt], &bl[j >> 1][(j & 1) * 2]);
            }
        }
    }
}

// ---------------------------------------------------------------------------
// conv cp.async stage issue (128 threads): phase p = (k = p/10, d-chunk = p%10)
// ---------------------------------------------------------------------------
__device__ __forceinline__ void conv_issue(int p, int b, int o0, int t0,
                                           int tid, u32 smbase) {
    int k = p / 10;
    int ph = p - k * 10;
    int d0 = ph * 32;
    const __nv_bfloat16* Ah = g_Whi + ((size_t)k * OP2 + o0) * DP + d0;
    const __nv_bfloat16* Al = g_Wlo + ((size_t)k * OP2 + o0) * DP + d0;
    const __nv_bfloat16* Bh = g_Ehi + ((size_t)b * ETR + t0 + k) * DP + d0;
    const __nv_bfloat16* Bl = g_Elo + ((size_t)b * ETR + t0 + k) * DP + d0;
    u32 sb = smbase + (u32)((p & 1) * C_STG);
#pragma unroll
    for (int it = 0; it < 4; it++) {
        int idx = tid + it * 128;       // 0..511 = 128 rows x 4 16B-chunks
        int row = idx >> 2;
        int qd = (idx & 3) * 8;
        u32 so = sb + (u32)((row * SSTR + qd) * 2);
        size_t go = (size_t)row * DP + qd;
        cpa16(so,        Ah + go);
        cpa16(so + C_AL, Al + go);
        cpa16(so + C_BH, Bh + go);
        cpa16(so + C_BL, Bl + go);
    }
    cpa_commit();
}

// ---------------------------------------------------------------------------
// Kernel 4: conv1d, 128 threads (4 warps, 64x64 tiles), pipelined
// ---------------------------------------------------------------------------
__global__ void __launch_bounds__(128, 2) k_conv(const float* __restrict__ conv_b) {
    extern __shared__ __align__(16) char dynsm[];
    int t0 = blockIdx.x * 128;
    int o0 = blockIdx.y * 128;
    int b  = blockIdx.z;
    int tid = threadIdx.x;
    int lane = tid & 31;
    int warp = tid >> 5;
    int warp_m = warp >> 1;
    int warp_n = warp & 1;
    int g = lane >> 2;
    int q = lane & 3;

    u32 smbase = smem_u32(dynsm);

    u32 aoff[4];
#pragma unroll
    for (int mt = 0; mt < 4; mt++) {
        aoff[mt] = (u32)(((warp_m * 64 + mt * 16 + (lane & 15)) * SSTR + (lane >> 4) * 8) * 2);
    }
    u32 boff[4];
    {
        int bidx = lane >> 3;
        int brow_add = (bidx >> 1) * 8 + (lane & 7);
        int bcol = (bidx & 1) * 8;
#pragma unroll
        for (int j2 = 0; j2 < 4; j2++) {
            boff[j2] = (u32)(((warp_n * 64 + j2 * 16 + brow_add) * SSTR + bcol) * 2);
        }
    }

    float acc[4][8][4];
#pragma unroll
    for (int mt = 0; mt < 4; mt++) {
#pragma unroll
        for (int j = 0; j < 8; j++) {
#pragma unroll
            for (int c = 0; c < 4; c++) { acc[mt][j][c] = 0.f; }
        }
    }

    const int NPH = 100;
    conv_issue(0, b, o0, t0, tid, smbase);

    for (int p = 0; p < NPH; p++) {
        if (p + 1 < NPH) {
            conv_issue(p + 1, b, o0, t0, tid, smbase);
            cpa_wait1();
        } else {
            cpa_wait0();
        }
        __syncthreads();

        u32 sb = smbase + (u32)((p & 1) * C_STG);
        mma_step64(sb, C_AL, C_BH, C_BL, aoff, boff, acc);
        __syncthreads();
    }

    // Epilogue: bias + relu, hi/lo split, transposed element stores to [t][o]
#pragma unroll
    for (int mt = 0; mt < 4; mt++) {
#pragma unroll
        for (int ch = 0; ch < 2; ch++) {
            int o = o0 + warp_m * 64 + mt * 16 + g + ch * 8;
            if (o < DD) {
                float bias = conv_b[o];
#pragma unroll
                for (int j = 0; j < 8; j++) {
#pragma unroll
                    for (int bb2 = 0; bb2 < 2; bb2++) {
                        int t = t0 + warp_n * 64 + j * 8 + q * 2 + bb2;
                        if (t < TP) {
                            float v = fmaxf(acc[mt][j][ch * 2 + bb2] + bias, 0.f);
                            __nv_bfloat16 h = __float2bfloat16(v);
                            size_t dst = ((size_t)b * TPAD + t) * DP + o;
                            g_Hthi[dst] = h;
                            g_Htlo[dst] = __float2bfloat16(v - __bfloat162float(h));
                        }
                    }
                }
            }
        }
    }
}

// ---------------------------------------------------------------------------
// attn cp.async stage issue (256 threads): phase p = (t-tile = p/10, d = p%10)
//   A = 256 l rows, B = 128 t rows
// ---------------------------------------------------------------------------
__device__ __forceinline__ void attn_issue(int p, int b, int l0,
                                           int tid, u32 smbase) {
    int tile = p / 10;
    int ph = p - tile * 10;
    int d0 = ph * 32;
    int t0 = tile * 128;
    const __nv_bfloat16* Ah = g_Uhi + (size_t)l0 * DP + d0;
    const __nv_bfloat16* Al = g_Ulo + (size_t)l0 * DP + d0;
    const __nv_bfloat16* Bh = g_Hthi + ((size_t)b * TPAD + t0) * DP + d0;
    const __nv_bfloat16* Bl = g_Htlo + ((size_t)b * TPAD + t0) * DP + d0;
    u32 sb = smbase + (u32)((p & 1) * A_STG);
#pragma unroll
    for (int it = 0; it < 4; it++) {
        int idx = tid + it * 256;       // 0..1023 = 256 rows x 4 chunks
        int row = idx >> 2;
        int qd = (idx & 3) * 8;
        u32 so = sb + (u32)((row * SSTR + qd) * 2);
        size_t go = (size_t)row * DP + qd;
        cpa16(so,        Ah + go);
        cpa16(so + A_AL, Al + go);
    }
#pragma unroll
    for (int it = 0; it < 2; it++) {
        int idx = tid + it * 256;       // 0..511 = 128 rows x 4 chunks
        int row = idx >> 2;
        int qd = (idx & 3) * 8;
        u32 so = sb + (u32)((row * SSTR + qd) * 2);
        size_t go = (size_t)row * DP + qd;
        cpa16(so + A_BH, Bh + go);
        cpa16(so + A_BL, Bl + go);
    }
    cpa_commit();
}

// ---------------------------------------------------------------------------
// Kernel 5: fused score-GEMM + online softmax
//   block: 256 l x 128 t-tile, 8 warps (4m x 2n, 64x64 tiles), pipelined
// ---------------------------------------------------------------------------
__global__ void __launch_bounds__(256, 1) k_attn(const float* __restrict__ fc_bias,
                                                 float* __restrict__ out) {
    extern __shared__ __align__(16) char dynsm[];
    __shared__ float s_m[256];
    __shared__ float s_e[256];
    __shared__ float s_s[256];
    __shared__ float p_m[2][256];
    __shared__ float p_e[2][256];
    __shared__ float p_s[2][256];

    int l0 = blockIdx.x * 256;
    int b  = blockIdx.y;
    int tid = threadIdx.x;
    int lane = tid & 31;
    int warp = tid >> 5;
    int warp_m = warp >> 1;
    int warp_n = warp & 1;
    int g = lane >> 2;
    int q = lane & 3;

    s_m[tid] = -INFINITY;
    s_e[tid] = 0.f;
    s_s[tid] = 0.f;

    u32 smbase = smem_u32(dynsm);

    u32 aoff[4];
#pragma unroll
    for (int mt = 0; mt < 4; mt++) {
        aoff[mt] = (u32)(((warp_m * 64 + mt * 16 + (lane & 15)) * SSTR + (lane >> 4) * 8) * 2);
    }
    u32 boff[4];
    {
        int bidx = lane >> 3;
        int brow_add = (bidx >> 1) * 8 + (lane & 7);
        int bcol = (bidx & 1) * 8;
#pragma unroll
        for (int j2 = 0; j2 < 4; j2++) {
            boff[j2] = (u32)(((warp_n * 64 + j2 * 16 + brow_add) * SSTR + bcol) * 2);
        }
    }

    const int NPH = 170;
    attn_issue(0, b, l0, tid, smbase);

    float acc[4][8][4];

    for (int p = 0; p < NPH; p++) {
        int tile = p / 10;
        int ph = p - tile * 10;

        if (ph == 0) {
#pragma unroll
            for (int mt = 0; mt < 4; mt++) {
#pragma unroll
                for (int j = 0; j < 8; j++) {
#pragma unroll
                    for (int c = 0; c < 4; c++) { acc[mt][j][c] = 0.f; }
                }
            }
        }

        if (p + 1 < NPH) {
            attn_issue(p + 1, b, l0, tid, smbase);
            cpa_wait1();
        } else {
            cpa_wait0();
        }
        __syncthreads();

        u32 sb = smbase + (u32)((p & 1) * A_STG);
        mma_step64(sb, A_AL, A_BH, A_BL, aoff, boff, acc);

        if (ph == 9) {
            int t0 = tile * 128;
#pragma unroll
            for (int mt = 0; mt < 4; mt++) {
#pragma unroll
                for (int ch = 0; ch < 2; ch++) {
                    int row = warp_m * 64 + mt * 16 + g + ch * 8;
                    float mx = -INFINITY;
#pragma unroll
                    for (int j = 0; j < 8; j++) {
#pragma unroll
                        for (int bb2 = 0; bb2 < 2; bb2++) {
                            int t = t0 + warp_n * 64 + j * 8 + q * 2 + bb2;
                            if (t < TP) { mx = fmaxf(mx, acc[mt][j][ch * 2 + bb2]); }
                        }
                    }
                    mx = fmaxf(mx, __shfl_xor_sync(0xffffffffu, mx, 1));
                    mx = fmaxf(mx, __shfl_xor_sync(0xffffffffu, mx, 2));

                    float pe = 0.f;
                    float ps = 0.f;
#pragma unroll
                    for (int j = 0; j < 8; j++) {
#pragma unroll
                        for (int bb2 = 0; bb2 < 2; bb2++) {
                            int t = t0 + warp_n * 64 + j * 8 + q * 2 + bb2;
                            if (t < TP) {
                                float v = acc[mt][j][ch * 2 + bb2];
                                float pv = __expf(v - mx);
                                pe += pv;
                                ps += pv * v;
                            }
                        }
                    }
                    pe += __shfl_xor_sync(0xffffffffu, pe, 1);
                    ps += __shfl_xor_sync(0xffffffffu, ps, 1);
                    pe += __shfl_xor_sync(0xffffffffu, pe, 2);
                    ps += __shfl_xor_sync(0xffffffffu, ps, 2);

                    if (q == 0) {
                        p_m[warp_n][row] = mx;
                        p_e[warp_n][row] = pe;
                        p_s[warp_n][row] = ps;
                    }
                }
            }
            __syncthreads();

            {
                float mo = s_m[tid];
                float eo = s_e[tid];
                float so = s_s[tid];
#pragma unroll
                for (int pp = 0; pp < 2; pp++) {
                    float mxp = p_m[pp][tid];
                    float pep = p_e[pp][tid];
                    float psp = p_s[pp][tid];
                    float mn = fmaxf(mo, mxp);
                    float e1 = __expf(mo - mn);
                    float e2 = __expf(mxp - mn);
                    eo = eo * e1 + pep * e2;
                    so = so * e1 + psp * e2;
                    mo = mn;
                }
                s_m[tid] = mo;
                s_e[tid] = eo;
                s_s[tid] = so;
            }
        }
        __syncthreads();
    }

    {
        int l = l0 + tid;
        if (l < LL) { out[b * LL + l] = s_s[tid] / s_e[tid] + fc_bias[l]; }
    }
}

// ---------------------------------------------------------------------------
// Launch
// ---------------------------------------------------------------------------
extern "C" void kernel_launch(void* const* d_in, const int* in_sizes, int n_in,
                              void* d_out, int out_size) {
    const int* ids = nullptr;
    const float* emb = nullptr;
    const float* cw = nullptr;
    const float* cb = nullptr;
    const float* U = nullptr;
    const float* fb = nullptr;
    for (int i = 0; i < n_in; i++) {
        int s = in_sizes[i];
        if (s == BB * TT) { ids = (const int*)d_in[i]; }
        else if (s == 50000 * DD) { emb = (const float*)d_in[i]; }
        else if (s == DD * DD * KK) { cw = (const float*)d_in[i]; }
        else if (s == DD) { cb = (const float*)d_in[i]; }
        else if (s == LL * DD) { U = (const float*)d_in[i]; }
        else if (s == LL) { fb = (const float*)d_in[i]; }
    }
    float* out = (float*)d_out;

    const int DYN_CONV = 2 * C_STG;   // 81920
    const int DYN_ATTN = 2 * A_STG;   // 122880
    cudaFuncSetAttribute(k_conv, cudaFuncAttributeMaxDynamicSharedMemorySize, DYN_CONV);
    cudaFuncSetAttribute(k_attn, cudaFuncAttributeMaxDynamicSharedMemorySize, DYN_ATTN);

    k_wsplit<<<(KK * DD * DD + 255) / 256, 256>>>(cw);
    k_usplit<<<(LL * DD + 255) / 256, 256>>>(U);
    k_gather<<<(BB * TT * DD + 255) / 256, 256>>>(ids, emb);
    k_conv<<<dim3(TPAD / 128, OP2 / 128, BB), 128, DYN_CONV>>>(cb);
    k_attn<<<dim3(LP / 256, BB), 256, DYN_ATTN>>>(fb, out);
}

// round 13
// speedup vs baseline: 1.2404x; 1.2404x over previous
#include <cuda_runtime.h>
#include <cuda_bf16.h>
#include <cstdint>
#include <math.h>

typedef unsigned int u32;

// Problem dims
#define BB   8
#define TT   2048
#define DD   300
#define KK   10
#define LL   8921
#define TP   2057     // TT + KK - 1
#define LP   8960     // L padded to 70*128
#define OP2  384      // o padded to 3*128
#define DP   320      // d padded to 20*16
#define TPAD 2176     // t' padded to 17*128
#define ETR  2208     // embed rows: 9 halo + 2048 + tail zeros

// Stage layout: A (hi+lo interleaved per row) 16KB, B 16KB; 3 stages
#define SB_B   16384
#define STG    32768
#define NSTG   3

// Scratch (device globals, zero-initialized; padding regions never written)
__device__ __align__(16) __nv_bfloat16 g_Ehi[BB * ETR * DP];   // [b][9+tau][d]
__device__ __align__(16) __nv_bfloat16 g_Elo[BB * ETR * DP];
__device__ __align__(16) __nv_bfloat16 g_Whi[KK * OP2 * DP];   // [k][o][i]
__device__ __align__(16) __nv_bfloat16 g_Wlo[KK * OP2 * DP];
__device__ __align__(16) __nv_bfloat16 g_Uhi[LP * DP];         // [l][d]
__device__ __align__(16) __nv_bfloat16 g_Ulo[LP * DP];
__device__ __align__(16) __nv_bfloat16 g_Hthi[BB * TPAD * DP]; // [b][t][o]
__device__ __align__(16) __nv_bfloat16 g_Htlo[BB * TPAD * DP];

// ---------------------------------------------------------------------------
// PTX helpers
// ---------------------------------------------------------------------------
__device__ __forceinline__ u32 smem_u32(const void* p) {
    return (u32)__cvta_generic_to_shared(p);
}

__device__ __forceinline__ void ldsm4(u32* r, u32 addr) {
    asm volatile("ldmatrix.sync.aligned.m8n8.x4.shared.b16 {%0,%1,%2,%3}, [%4];"
                 : "=r"(r[0]), "=r"(r[1]), "=r"(r[2]), "=r"(r[3])
                 : "r"(addr));
}

__device__ __forceinline__ void mma16816(float* d, const u32* a, const u32* b) {
    asm volatile(
        "mma.sync.aligned.m16n8k16.row.col.f32.bf16.bf16.f32 "
        "{%0,%1,%2,%3}, {%4,%5,%6,%7}, {%8,%9}, {%0,%1,%2,%3};"
        : "+f"(d[0]), "+f"(d[1]), "+f"(d[2]), "+f"(d[3])
        : "r"(a[0]), "r"(a[1]), "r"(a[2]), "r"(a[3]), "r"(b[0]), "r"(b[1]));
}

__device__ __forceinline__ void cpa16(u32 dst, const void* src) {
    asm volatile("cp.async.cg.shared.global [%0], [%1], 16;" :: "r"(dst), "l"(src));
}
__device__ __forceinline__ void cpa_commit() {
    asm volatile("cp.async.commit_group;");
}
__device__ __forceinline__ void cpa_wait1() {
    asm volatile("cp.async.wait_group 1;");
}
__device__ __forceinline__ void cpa_wait0() {
    asm volatile("cp.async.wait_group 0;");
}

// ---------------------------------------------------------------------------
// Kernel 1: embedding gather + bf16 hi/lo split -> Ehi/Elo[b][9+tau][d]
// ---------------------------------------------------------------------------
__global__ void k_gather(const int* __restrict__ ids, const float* __restrict__ emb) {
    int idx = blockIdx.x * 256 + threadIdx.x;
    if (idx >= BB * TT * DD) { return; }
    int d = idx % DD;
    int tok = idx / DD;
    int b = tok / TT;
    int tau = tok - b * TT;
    int row = ids[tok];
    float v = emb[row * DD + d];
    __nv_bfloat16 h = __float2bfloat16(v);
    size_t o = ((size_t)b * ETR + 9 + tau) * DP + d;
    g_Ehi[o] = h;
    g_Elo[o] = __float2bfloat16(v - __bfloat162float(h));
}

// ---------------------------------------------------------------------------
// Kernel 2: conv_w (O,I,K) fp32 -> Whi/Wlo[k][o][i]
// ---------------------------------------------------------------------------
__global__ void k_wsplit(const float* __restrict__ w) {
    int idx = blockIdx.x * 256 + threadIdx.x;
    if (idx >= KK * DD * DD) { return; }
    int i = idx % DD;
    int rem = idx / DD;
    int o = rem % DD;
    int k = rem / DD;
    float v = w[(o * DD + i) * KK + k];
    __nv_bfloat16 h = __float2bfloat16(v);
    size_t dst = ((size_t)k * OP2 + o) * DP + i;
    g_Whi[dst] = h;
    g_Wlo[dst] = __float2bfloat16(v - __bfloat162float(h));
}

// ---------------------------------------------------------------------------
// Kernel 3: U fp32 [l][d] -> bf16 hi/lo split [l][DP]
// ---------------------------------------------------------------------------
__global__ void k_usplit(const float* __restrict__ U) {
    int idx = blockIdx.x * 256 + threadIdx.x;
    if (idx >= LL * DD) { return; }
    int l = idx / DD;
    int d = idx - l * DD;
    float u = U[idx];
    __nv_bfloat16 h = __float2bfloat16(u);
    g_Uhi[l * DP + d] = h;
    g_Ulo[l * DP + d] = __float2bfloat16(u - __bfloat162float(h));
}

// ---------------------------------------------------------------------------
// Stage fill via cp.async: 2 arrays (A,B) x 128 rows x 8 chunks of 16B,
// chunks 0-3 = hi (32 bf16), 4-7 = lo; physical chunk = c ^ (row&7).
// ---------------------------------------------------------------------------
__device__ __forceinline__ void stage_fill(u32 sb, int tid,
                                           const __nv_bfloat16* Ahi,
                                           const __nv_bfloat16* Alo,
                                           const __nv_bfloat16* Bhi,
                                           const __nv_bfloat16* Blo) {
#pragma unroll
    for (int it = 0; it < 8; it++) {
        int idx = tid + it * 256;
        int rem = idx & 1023;
        int row = rem >> 3;
        int c = rem & 7;
        int dcol = (c & 3) * 8;
        u32 dst = sb + (u32)((it >> 2) * SB_B) + (u32)(row * 128)
                + (u32)(((c ^ (row & 7)) << 4));
        size_t go = (size_t)row * DP + dcol;
        const __nv_bfloat16* src;
        if (it < 4) {
            src = (c < 4) ? (Ahi + go) : (Alo + go);
        } else {
            src = (c < 4) ? (Bhi + go) : (Blo + go);
        }
        cpa16(dst, src);
    }
    cpa_commit();
}

// ---------------------------------------------------------------------------
// 32x64 warp-tile phase: hi/lo 3-pass, swizzled smem addressing
//   rA[mt] = row*128 (A rows), rB[j2] = SB_B + row*128 (B rows), x = lane&7
// ---------------------------------------------------------------------------
__device__ __forceinline__ void mma_phase(u32 sb, const u32* rA, const u32* rB,
                                          u32 x, u32 c0a, u32 c0b,
                                          float acc[2][8][4]) {
#pragma unroll
    for (int kc = 0; kc < 2; kc++) {
        u32 ca = c0a + (u32)(kc * 2);
        u32 cb = c0b + (u32)(kc * 2);
        u32 ah0[4];
        u32 ah1[4];
        u32 al0[4];
        u32 al1[4];
        u32 bh[4][4];
        u32 bl[4][4];

        ldsm4(ah0, sb + rA[0] + ((ca ^ x) << 4));
        ldsm4(ah1, sb + rA[1] + ((ca ^ x) << 4));
#pragma unroll
        for (int j2 = 0; j2 < 4; j2++) {
            ldsm4(bh[j2], sb + rB[j2] + ((cb ^ x) << 4));
        }

        // pass 1: hi*hi
#pragma unroll
        for (int j = 0; j < 8; j++) {
            const u32* bp = &bh[j >> 1][(j & 1) * 2];
            mma16816(acc[0][j], ah0, bp);
            mma16816(acc[1][j], ah1, bp);
        }

        // pass 2: lo*hi
        ldsm4(al0, sb + rA[0] + (((ca + 4) ^ x) << 4));
        ldsm4(al1, sb + rA[1] + (((ca + 4) ^ x) << 4));
#pragma unroll
        for (int j = 0; j < 8; j++) {
            const u32* bp = &bh[j >> 1][(j & 1) * 2];
            mma16816(acc[0][j], al0, bp);
            mma16816(acc[1][j], al1, bp);
        }

        // pass 3: hi*lo
#pragma unroll
        for (int j2 = 0; j2 < 4; j2++) {
            ldsm4(bl[j2], sb + rB[j2] + (((cb + 4) ^ x) << 4));
        }
#pragma unroll
        for (int j = 0; j < 8; j++) {
            const u32* bp = &bl[j >> 1][(j & 1) * 2];
            mma16816(acc[0][j], ah0, bp);
            mma16816(acc[1][j], ah1, bp);
        }
    }
}

// ---------------------------------------------------------------------------
// Kernel 4: conv1d, 256 threads (8 warps, 32x64 tiles), 3-stage pipeline
//   C[o,t] = sum_k sum_i W[k][o][i] * E[t+k][i]; 100 phases (k x d-chunk)
// ---------------------------------------------------------------------------
__global__ void __launch_bounds__(256, 2) k_conv(const float* __restrict__ conv_b) {
    extern __shared__ __align__(16) char dynsm[];
    int t0 = blockIdx.x * 128;
    int o0 = blockIdx.y * 128;
    int b  = blockIdx.z;
    int tid = threadIdx.x;
    int lane = tid & 31;
    int warp = tid >> 5;
    int warp_m = warp >> 1;
    int warp_n = warp & 1;
    int g = lane >> 2;
    int q = lane & 3;

    u32 smbase = smem_u32(dynsm);
    u32 x = (u32)(lane & 7);
    u32 c0a = (u32)(lane >> 4);
    u32 c0b = (u32)((lane >> 3) & 1);

    u32 rA[2];
#pragma unroll
    for (int mt = 0; mt < 2; mt++) {
        rA[mt] = (u32)((warp_m * 32 + mt * 16 + (lane & 15)) * 128);
    }
    u32 rB[4];
    {
        int brow = ((lane >> 4) & 1) * 8 + (lane & 7);
#pragma unroll
        for (int j2 = 0; j2 < 4; j2++) {
            rB[j2] = (u32)(SB_B + (warp_n * 64 + j2 * 16 + brow) * 128);
        }
    }

    float acc[2][8][4];
#pragma unroll
    for (int mt = 0; mt < 2; mt++) {
#pragma unroll
        for (int j = 0; j < 8; j++) {
#pragma unroll
            for (int c = 0; c < 4; c++) { acc[mt][j][c] = 0.f; }
        }
    }

    const int NPH = 100;

    // phase p -> (k = p/10, d-chunk = p%10)
#pragma unroll 1
    for (int pre = 0; pre < 2; pre++) {
        int k = pre / 10;
        int d0 = (pre % 10) * 32;
        stage_fill(smbase + (u32)(pre * STG), tid,
                   g_Whi + ((size_t)k * OP2 + o0) * DP + d0,
                   g_Wlo + ((size_t)k * OP2 + o0) * DP + d0,
                   g_Ehi + ((size_t)b * ETR + t0 + k) * DP + d0,
                   g_Elo + ((size_t)b * ETR + t0 + k) * DP + d0);
    }

    int slot = 0;
    int islot = 2;
#pragma unroll 1
    for (int p = 0; p < NPH; p++) {
        if (p < NPH - 1) { cpa_wait1(); } else { cpa_wait0(); }
        __syncthreads();

        if (p + 2 < NPH) {
            int pn = p + 2;
            int k = pn / 10;
            int d0 = (pn - k * 10) * 32;
            stage_fill(smbase + (u32)(islot * STG), tid,
                       g_Whi + ((size_t)k * OP2 + o0) * DP + d0,
                       g_Wlo + ((size_t)k * OP2 + o0) * DP + d0,
                       g_Ehi + ((size_t)b * ETR + t0 + k) * DP + d0,
                       g_Elo + ((size_t)b * ETR + t0 + k) * DP + d0);
        }

        mma_phase(smbase + (u32)(slot * STG), rA, rB, x, c0a, c0b, acc);

        slot++;
        if (slot == NSTG) { slot = 0; }
        islot++;
        if (islot == NSTG) { islot = 0; }
    }

    // Epilogue: bias + relu, hi/lo split, transposed element stores to [t][o]
#pragma unroll
    for (int mt = 0; mt < 2; mt++) {
#pragma unroll
        for (int ch = 0; ch < 2; ch++) {
            int o = o0 + warp_m * 32 + mt * 16 + g + ch * 8;
            if (o < DD) {
                float bias = conv_b[o];
#pragma unroll
                for (int j = 0; j < 8; j++) {
#pragma unroll
                    for (int bb2 = 0; bb2 < 2; bb2++) {
                        int t = t0 + warp_n * 64 + j * 8 + q * 2 + bb2;
                        if (t < TP) {
                            float v = fmaxf(acc[mt][j][ch * 2 + bb2] + bias, 0.f);
                            __nv_bfloat16 h = __float2bfloat16(v);
                            size_t dst = ((size_t)b * TPAD + t) * DP + o;
                            g_Hthi[dst] = h;
                            g_Htlo[dst] = __float2bfloat16(v - __bfloat162float(h));
                        }
                    }
                }
            }
        }
    }
}

// ---------------------------------------------------------------------------
// Kernel 5: fused score-GEMM + online softmax, 3-stage pipeline
//   block: 128 l x 128 t-tile, 8 warps (4m x 2n, 32x64), 170 phases
// ---------------------------------------------------------------------------
__global__ void __launch_bounds__(256, 2) k_attn(const float* __restrict__ fc_bias,
                                                 float* __restrict__ out) {
    extern __shared__ __align__(16) char dynsm[];
    __shared__ float s_m[128];
    __shared__ float s_e[128];
    __shared__ float s_s[128];
    __shared__ float p_m[2][128];
    __shared__ float p_e[2][128];
    __shared__ float p_s[2][128];

    int l0 = blockIdx.x * 128;
    int b  = blockIdx.y;
    int tid = threadIdx.x;
    int lane = tid & 31;
    int warp = tid >> 5;
    int warp_m = warp >> 1;
    int warp_n = warp & 1;
    int g = lane >> 2;
    int q = lane & 3;

    if (tid < 128) {
        s_m[tid] = -INFINITY;
        s_e[tid] = 0.f;
        s_s[tid] = 0.f;
    }

    u32 smbase = smem_u32(dynsm);
    u32 x = (u32)(lane & 7);
    u32 c0a = (u32)(lane >> 4);
    u32 c0b = (u32)((lane >> 3) & 1);

    u32 rA[2];
#pragma unroll
    for (int mt = 0; mt < 2; mt++) {
        rA[mt] = (u32)((warp_m * 32 + mt * 16 + (lane & 15)) * 128);
    }
    u32 rB[4];
    {
        int brow = ((lane >> 4) & 1) * 8 + (lane & 7);
#pragma unroll
        for (int j2 = 0; j2 < 4; j2++) {
            rB[j2] = (u32)(SB_B + (warp_n * 64 + j2 * 16 + brow) * 128);
        }
    }

    const __nv_bfloat16* BHbase = g_Hthi + (size_t)b * TPAD * DP;
    const __nv_bfloat16* BLbase = g_Htlo + (size_t)b * TPAD * DP;

    const int NPH = 170;

    // phase p -> (t-tile = p/10, d-chunk = p%10)
#pragma unroll 1
    for (int pre = 0; pre < 2; pre++) {
        int d0 = (pre % 10) * 32;
        stage_fill(smbase + (u32)(pre * STG), tid,
                   g_Uhi + (size_t)l0 * DP + d0,
                   g_Ulo + (size_t)l0 * DP + d0,
                   BHbase + d0,
                   BLbase + d0);
    }

    float acc[2][8][4];
    int slot = 0;
    int islot = 2;

#pragma unroll 1
    for (int p = 0; p < NPH; p++) {
        int tile = p / 10;
        int ph = p - tile * 10;

        if (ph == 0) {
#pragma unroll
            for (int mt = 0; mt < 2; mt++) {
#pragma unroll
                for (int j = 0; j < 8; j++) {
#pragma unroll
                    for (int c = 0; c < 4; c++) { acc[mt][j][c] = 0.f; }
                }
            }
        }

        if (p < NPH - 1) { cpa_wait1(); } else { cpa_wait0(); }
        __syncthreads();

        if (p + 2 < NPH) {
            int pn = p + 2;
            int tn = pn / 10;
            int d0 = (pn - tn * 10) * 32;
            int tt0 = tn * 128;
            stage_fill(smbase + (u32)(islot * STG), tid,
                       g_Uhi + (size_t)l0 * DP + d0,
                       g_Ulo + (size_t)l0 * DP + d0,
                       BHbase + (size_t)tt0 * DP + d0,
                       BLbase + (size_t)tt0 * DP + d0);
        }

        mma_phase(smbase + (u32)(slot * STG), rA, rB, x, c0a, c0b, acc);

        if (ph == 9) {
            int t0 = tile * 128;
#pragma unroll
            for (int mt = 0; mt < 2; mt++) {
#pragma unroll
                for (int ch = 0; ch < 2; ch++) {
                    int row = warp_m * 32 + mt * 16 + g + ch * 8;
                    float mx = -INFINITY;
#pragma unroll
                    for (int j = 0; j < 8; j++) {
#pragma unroll
                        for (int bb2 = 0; bb2 < 2; bb2++) {
                            int t = t0 + warp_n * 64 + j * 8 + q * 2 + bb2;
                            if (t < TP) { mx = fmaxf(mx, acc[mt][j][ch * 2 + bb2]); }
                        }
                    }
                    mx = fmaxf(mx, __shfl_xor_sync(0xffffffffu, mx, 1));
                    mx = fmaxf(mx, __shfl_xor_sync(0xffffffffu, mx, 2));

                    float pe = 0.f;
                    float ps = 0.f;
#pragma unroll
                    for (int j = 0; j < 8; j++) {
#pragma unroll
                        for (int bb2 = 0; bb2 < 2; bb2++) {
                            int t = t0 + warp_n * 64 + j * 8 + q * 2 + bb2;
                            if (t < TP) {
                                float v = acc[mt][j][ch * 2 + bb2];
                                float pv = __expf(v - mx);
                                pe += pv;
                                ps += pv * v;
                            }
                        }
                    }
                    pe += __shfl_xor_sync(0xffffffffu, pe, 1);
                    ps += __shfl_xor_sync(0xffffffffu, ps, 1);
                    pe += __shfl_xor_sync(0xffffffffu, pe, 2);
                    ps += __shfl_xor_sync(0xffffffffu, ps, 2);

                    if (q == 0) {
                        p_m[warp_n][row] = mx;
                        p_e[warp_n][row] = pe;
                        p_s[warp_n][row] = ps;
                    }
                }
            }
            __syncthreads();

            if (tid < 128) {
                float mo = s_m[tid];
                float eo = s_e[tid];
                float so = s_s[tid];
#pragma unroll
                for (int pp = 0; pp < 2; pp++) {
                    float mxp = p_m[pp][tid];
                    float pep = p_e[pp][tid];
                    float psp = p_s[pp][tid];
                    float mn = fmaxf(mo, mxp);
                    float e1 = __expf(mo - mn);
                    float e2 = __expf(mxp - mn);
                    eo = eo * e1 + pep * e2;
                    so = so * e1 + psp * e2;
                    mo = mn;
                }
                s_m[tid] = mo;
                s_e[tid] = eo;
                s_s[tid] = so;
            }
        }

        slot++;
        if (slot == NSTG) { slot = 0; }
        islot++;
        if (islot == NSTG) { islot = 0; }
    }

    if (tid < 128) {
        int l = l0 + tid;
        if (l < LL) { out[b * LL + l] = s_s[tid] / s_e[tid] + fc_bias[l]; }
    }
}

// ---------------------------------------------------------------------------
// Launch
// ---------------------------------------------------------------------------
extern "C" void kernel_launch(void* const* d_in, const int* in_sizes, int n_in,
                              void* d_out, int out_size) {
    const int* ids = nullptr;
    const float* emb = nullptr;
    const float* cw = nullptr;
    const float* cb = nullptr;
    const float* U = nullptr;
    const float* fb = nullptr;
    for (int i = 0; i < n_in; i++) {
        int s = in_sizes[i];
        if (s == BB * TT) { ids = (const int*)d_in[i]; }
        else if (s == 50000 * DD) { emb = (const float*)d_in[i]; }
        else if (s == DD * DD * KK) { cw = (const float*)d_in[i]; }
        else if (s == DD) { cb = (const float*)d_in[i]; }
        else if (s == LL * DD) { U = (const float*)d_in[i]; }
        else if (s == LL) { fb = (const float*)d_in[i]; }
    }
    float* out = (float*)d_out;

    const int DYN = NSTG * STG;   // 98304 bytes
    cudaFuncSetAttribute(k_conv, cudaFuncAttributeMaxDynamicSharedMemorySize, DYN);
    cudaFuncSetAttribute(k_attn, cudaFuncAttributeMaxDynamicSharedMemorySize, DYN);

    k_wsplit<<<(KK * DD * DD + 255) / 256, 256>>>(cw);
    k_usplit<<<(LL * DD + 255) / 256, 256>>>(U);
    k_gather<<<(BB * TT * DD + 255) / 256, 256>>>(ids, emb);
    k_conv<<<dim3(TPAD / 128, OP2 / 128, BB), 256, DYN>>>(cb);
    k_attn<<<dim3(LP / 128, BB), 256, DYN>>>(fb, out);
}

// round 14
// speedup vs baseline: 1.2734x; 1.0266x over previous
#include <cuda_runtime.h>
#include <cuda_bf16.h>
#include <cstdint>
#include <math.h>

typedef unsigned int u32;

// Problem dims
#define BB   8
#define TT   2048
#define DD   300
#define KK   10
#define LL   8921
#define TP   2057     // TT + KK - 1
#define LP   8960     // L padded to 70*128
#define OP2  384      // o padded to 3*128
#define DP   320      // d padded to 20*16
#define TPAD 2176     // t' padded to 34*64
#define ETR  2208     // embed rows: 9 halo + 2048 + tail zeros

// Attn stage: A 128 rows (16KB) + B 128 rows (16KB); 3 stages
#define A_SBB  16384
#define A_STG  32768
// Conv stage: A 128 rows (16KB) + B 64 rows (8KB); 3 stages
#define C_SBB  16384
#define C_STG  24576
#define NSTG   3

// Scratch (device globals, zero-initialized; padding regions never written)
__device__ __align__(16) __nv_bfloat16 g_Ehi[BB * ETR * DP];   // [b][9+tau][d]
__device__ __align__(16) __nv_bfloat16 g_Elo[BB * ETR * DP];
__device__ __align__(16) __nv_bfloat16 g_Whi[KK * OP2 * DP];   // [k][o][i]
__device__ __align__(16) __nv_bfloat16 g_Wlo[KK * OP2 * DP];
__device__ __align__(16) __nv_bfloat16 g_Uhi[LP * DP];         // [l][d]
__device__ __align__(16) __nv_bfloat16 g_Ulo[LP * DP];
__device__ __align__(16) __nv_bfloat16 g_Hthi[BB * TPAD * DP]; // [b][t][o]
__device__ __align__(16) __nv_bfloat16 g_Htlo[BB * TPAD * DP];

// ---------------------------------------------------------------------------
// PTX helpers
// ---------------------------------------------------------------------------
__device__ __forceinline__ u32 smem_u32(const void* p) {
    return (u32)__cvta_generic_to_shared(p);
}

__device__ __forceinline__ void ldsm4(u32* r, u32 addr) {
    asm volatile("ldmatrix.sync.aligned.m8n8.x4.shared.b16 {%0,%1,%2,%3}, [%4];"
                 : "=r"(r[0]), "=r"(r[1]), "=r"(r[2]), "=r"(r[3])
                 : "r"(addr));
}

__device__ __forceinline__ void mma16816(float* d, const u32* a, const u32* b) {
    asm volatile(
        "mma.sync.aligned.m16n8k16.row.col.f32.bf16.bf16.f32 "
        "{%0,%1,%2,%3}, {%4,%5,%6,%7}, {%8,%9}, {%0,%1,%2,%3};"
        : "+f"(d[0]), "+f"(d[1]), "+f"(d[2]), "+f"(d[3])
        : "r"(a[0]), "r"(a[1]), "r"(a[2]), "r"(a[3]), "r"(b[0]), "r"(b[1]));
}

__device__ __forceinline__ void cpa16(u32 dst, const void* src) {
    asm volatile("cp.async.cg.shared.global [%0], [%1], 16;" :: "r"(dst), "l"(src));
}
__device__ __forceinline__ void cpa_commit() {
    asm volatile("cp.async.commit_group;");
}
__device__ __forceinline__ void cpa_wait1() {
    asm volatile("cp.async.wait_group 1;");
}
__device__ __forceinline__ void cpa_wait0() {
    asm volatile("cp.async.wait_group 0;");
}

// ---------------------------------------------------------------------------
// Kernel 1: embedding gather + bf16 hi/lo split -> Ehi/Elo[b][9+tau][d]
// ---------------------------------------------------------------------------
__global__ void k_gather(const int* __restrict__ ids, const float* __restrict__ emb) {
    int idx = blockIdx.x * 256 + threadIdx.x;
    if (idx >= BB * TT * DD) { return; }
    int d = idx % DD;
    int tok = idx / DD;
    int b = tok / TT;
    int tau = tok - b * TT;
    int row = ids[tok];
    float v = emb[row * DD + d];
    __nv_bfloat16 h = __float2bfloat16(v);
    size_t o = ((size_t)b * ETR + 9 + tau) * DP + d;
    g_Ehi[o] = h;
    g_Elo[o] = __float2bfloat16(v - __bfloat162float(h));
}

// ---------------------------------------------------------------------------
// Kernel 2: conv_w (O,I,K) fp32 -> Whi/Wlo[k][o][i]
// ---------------------------------------------------------------------------
__global__ void k_wsplit(const float* __restrict__ w) {
    int idx = blockIdx.x * 256 + threadIdx.x;
    if (idx >= KK * DD * DD) { return; }
    int i = idx % DD;
    int rem = idx / DD;
    int o = rem % DD;
    int k = rem / DD;
    float v = w[(o * DD + i) * KK + k];
    __nv_bfloat16 h = __float2bfloat16(v);
    size_t dst = ((size_t)k * OP2 + o) * DP + i;
    g_Whi[dst] = h;
    g_Wlo[dst] = __float2bfloat16(v - __bfloat162float(h));
}

// ---------------------------------------------------------------------------
// Kernel 3: U fp32 [l][d] -> bf16 hi/lo split [l][DP]
// ---------------------------------------------------------------------------
__global__ void k_usplit(const float* __restrict__ U) {
    int idx = blockIdx.x * 256 + threadIdx.x;
    if (idx >= LL * DD) { return; }
    int l = idx / DD;
    int d = idx - l * DD;
    float u = U[idx];
    __nv_bfloat16 h = __float2bfloat16(u);
    g_Uhi[l * DP + d] = h;
    g_Ulo[l * DP + d] = __float2bfloat16(u - __bfloat162float(h));
}

// ---------------------------------------------------------------------------
// Conv stage fill: A 128 rows, B 64 rows; chunk swizzle phys = c ^ (row&7)
// ---------------------------------------------------------------------------
__device__ __forceinline__ void stage_fill_c(u32 sb, int tid,
                                             const __nv_bfloat16* Ahi,
                                             const __nv_bfloat16* Alo,
                                             const __nv_bfloat16* Bhi,
                                             const __nv_bfloat16* Blo) {
#pragma unroll
    for (int it = 0; it < 4; it++) {
        int idx = tid + it * 256;
        int row = idx >> 3;
        int c = idx & 7;
        u32 dst = sb + (u32)(row * 128) + (u32)(((c ^ (row & 7)) << 4));
        size_t go = (size_t)row * DP + (c & 3) * 8;
        cpa16(dst, (c < 4) ? (Ahi + go) : (Alo + go));
    }
#pragma unroll
    for (int it = 0; it < 2; it++) {
        int idx = tid + it * 256;
        int row = idx >> 3;
        int c = idx & 7;
        u32 dst = sb + (u32)C_SBB + (u32)(row * 128) + (u32)(((c ^ (row & 7)) << 4));
        size_t go = (size_t)row * DP + (c & 3) * 8;
        cpa16(dst, (c < 4) ? (Bhi + go) : (Blo + go));
    }
    cpa_commit();
}

// ---------------------------------------------------------------------------
// Attn stage fill: A 128 rows, B 128 rows
// ---------------------------------------------------------------------------
__device__ __forceinline__ void stage_fill_a(u32 sb, int tid,
                                             const __nv_bfloat16* Ahi,
                                             const __nv_bfloat16* Alo,
                                             const __nv_bfloat16* Bhi,
                                             const __nv_bfloat16* Blo) {
#pragma unroll
    for (int it = 0; it < 8; it++) {
        int idx = tid + it * 256;
        int rem = idx & 1023;
        int row = rem >> 3;
        int c = rem & 7;
        u32 dst = sb + (u32)((it >> 2) * A_SBB) + (u32)(row * 128)
                + (u32)(((c ^ (row & 7)) << 4));
        size_t go = (size_t)row * DP + (c & 3) * 8;
        const __nv_bfloat16* src;
        if (it < 4) {
            src = (c < 4) ? (Ahi + go) : (Alo + go);
        } else {
            src = (c < 4) ? (Bhi + go) : (Blo + go);
        }
        cpa16(dst, src);
    }
    cpa_commit();
}

// ---------------------------------------------------------------------------
// Conv mma phase: warp tile 32x32 (2 m-frags, 2 B j2-frags, j 0..3)
// ---------------------------------------------------------------------------
__device__ __forceinline__ void mma_phase_c(u32 sb, const u32* rA, const u32* rB,
                                            u32 x, u32 c0a, u32 c0b,
                                            float acc[2][4][4]) {
#pragma unroll
    for (int kc = 0; kc < 2; kc++) {
        u32 ca = c0a + (u32)(kc * 2);
        u32 cb = c0b + (u32)(kc * 2);
        u32 ah0[4];
        u32 ah1[4];
        u32 al0[4];
        u32 al1[4];
        u32 bh[2][4];
        u32 bl[2][4];

        ldsm4(ah0, sb + rA[0] + ((ca ^ x) << 4));
        ldsm4(ah1, sb + rA[1] + ((ca ^ x) << 4));
        ldsm4(bh[0], sb + rB[0] + ((cb ^ x) << 4));
        ldsm4(bh[1], sb + rB[1] + ((cb ^ x) << 4));

#pragma unroll
        for (int j = 0; j < 4; j++) {
            const u32* bp = &bh[j >> 1][(j & 1) * 2];
            mma16816(acc[0][j], ah0, bp);
            mma16816(acc[1][j], ah1, bp);
        }

        ldsm4(al0, sb + rA[0] + (((ca + 4) ^ x) << 4));
        ldsm4(al1, sb + rA[1] + (((ca + 4) ^ x) << 4));
#pragma unroll
        for (int j = 0; j < 4; j++) {
            const u32* bp = &bh[j >> 1][(j & 1) * 2];
            mma16816(acc[0][j], al0, bp);
            mma16816(acc[1][j], al1, bp);
        }

        ldsm4(bl[0], sb + rB[0] + (((cb + 4) ^ x) << 4));
        ldsm4(bl[1], sb + rB[1] + (((cb + 4) ^ x) << 4));
#pragma unroll
        for (int j = 0; j < 4; j++) {
            const u32* bp = &bl[j >> 1][(j & 1) * 2];
            mma16816(acc[0][j], ah0, bp);
            mma16816(acc[1][j], ah1, bp);
        }
    }
}

// ---------------------------------------------------------------------------
// Attn mma phase: warp tile 32x64 (2 m-frags, 4 B j2-frags, j 0..7)
// ---------------------------------------------------------------------------
__device__ __forceinline__ void mma_phase_a(u32 sb, const u32* rA, const u32* rB,
                                            u32 x, u32 c0a, u32 c0b,
                                            float acc[2][8][4]) {
#pragma unroll
    for (int kc = 0; kc < 2; kc++) {
        u32 ca = c0a + (u32)(kc * 2);
        u32 cb = c0b + (u32)(kc * 2);
        u32 ah0[4];
        u32 ah1[4];
        u32 al0[4];
        u32 al1[4];
        u32 bh[4][4];
        u32 bl[4][4];

        ldsm4(ah0, sb + rA[0] + ((ca ^ x) << 4));
        ldsm4(ah1, sb + rA[1] + ((ca ^ x) << 4));
#pragma unroll
        for (int j2 = 0; j2 < 4; j2++) {
            ldsm4(bh[j2], sb + rB[j2] + ((cb ^ x) << 4));
        }

#pragma unroll
        for (int j = 0; j < 8; j++) {
            const u32* bp = &bh[j >> 1][(j & 1) * 2];
            mma16816(acc[0][j], ah0, bp);
            mma16816(acc[1][j], ah1, bp);
        }

        ldsm4(al0, sb + rA[0] + (((ca + 4) ^ x) << 4));
        ldsm4(al1, sb + rA[1] + (((ca + 4) ^ x) << 4));
#pragma unroll
        for (int j = 0; j < 8; j++) {
            const u32* bp = &bh[j >> 1][(j & 1) * 2];
            mma16816(acc[0][j], al0, bp);
            mma16816(acc[1][j], al1, bp);
        }

#pragma unroll
        for (int j2 = 0; j2 < 4; j2++) {
            ldsm4(bl[j2], sb + rB[j2] + (((cb + 4) ^ x) << 4));
        }
#pragma unroll
        for (int j = 0; j < 8; j++) {
            const u32* bp = &bl[j >> 1][(j & 1) * 2];
            mma16816(acc[0][j], ah0, bp);
            mma16816(acc[1][j], ah1, bp);
        }
    }
}

// ---------------------------------------------------------------------------
// Kernel 4: conv1d, block 128o x 64t (8 warps, 32x32 tiles), 3-stage pipeline
//   grid 34 x 3 x 8 = 816 blocks (wave quantization 92%)
// ---------------------------------------------------------------------------
__global__ void __launch_bounds__(256, 2) k_conv(const float* __restrict__ conv_b) {
    extern __shared__ __align__(16) char dynsm[];
    int t0 = blockIdx.x * 64;
    int o0 = blockIdx.y * 128;
    int b  = blockIdx.z;
    int tid = threadIdx.x;
    int lane = tid & 31;
    int warp = tid >> 5;
    int warp_m = warp >> 1;
    int warp_n = warp & 1;
    int g = lane >> 2;
    int q = lane & 3;

    u32 smbase = smem_u32(dynsm);
    u32 x = (u32)(lane & 7);
    u32 c0a = (u32)(lane >> 4);
    u32 c0b = (u32)((lane >> 3) & 1);

    u32 rA[2];
#pragma unroll
    for (int mt = 0; mt < 2; mt++) {
        rA[mt] = (u32)((warp_m * 32 + mt * 16 + (lane & 15)) * 128);
    }
    u32 rB[2];
    {
        int brow = ((lane >> 4) & 1) * 8 + (lane & 7);
#pragma unroll
        for (int j2 = 0; j2 < 2; j2++) {
            rB[j2] = (u32)(C_SBB + (warp_n * 32 + j2 * 16 + brow) * 128);
        }
    }

    float acc[2][4][4];
#pragma unroll
    for (int mt = 0; mt < 2; mt++) {
#pragma unroll
        for (int j = 0; j < 4; j++) {
#pragma unroll
            for (int c = 0; c < 4; c++) { acc[mt][j][c] = 0.f; }
        }
    }

    const int NPH = 100;

#pragma unroll 1
    for (int pre = 0; pre < 2; pre++) {
        int k = pre / 10;
        int d0 = (pre % 10) * 32;
        stage_fill_c(smbase + (u32)(pre * C_STG), tid,
                     g_Whi + ((size_t)k * OP2 + o0) * DP + d0,
                     g_Wlo + ((size_t)k * OP2 + o0) * DP + d0,
                     g_Ehi + ((size_t)b * ETR + t0 + k) * DP + d0,
                     g_Elo + ((size_t)b * ETR + t0 + k) * DP + d0);
    }

    int slot = 0;
    int islot = 2;
#pragma unroll 1
    for (int p = 0; p < NPH; p++) {
        if (p < NPH - 1) { cpa_wait1(); } else { cpa_wait0(); }
        __syncthreads();

        if (p + 2 < NPH) {
            int pn = p + 2;
            int k = pn / 10;
            int d0 = (pn - k * 10) * 32;
            stage_fill_c(smbase + (u32)(islot * C_STG), tid,
                         g_Whi + ((size_t)k * OP2 + o0) * DP + d0,
                         g_Wlo + ((size_t)k * OP2 + o0) * DP + d0,
                         g_Ehi + ((size_t)b * ETR + t0 + k) * DP + d0,
                         g_Elo + ((size_t)b * ETR + t0 + k) * DP + d0);
        }

        mma_phase_c(smbase + (u32)(slot * C_STG), rA, rB, x, c0a, c0b, acc);

        slot++;
        if (slot == NSTG) { slot = 0; }
        islot++;
        if (islot == NSTG) { islot = 0; }
    }

    // Epilogue: bias + relu, hi/lo split, transposed element stores to [t][o]
#pragma unroll
    for (int mt = 0; mt < 2; mt++) {
#pragma unroll
        for (int ch = 0; ch < 2; ch++) {
            int o = o0 + warp_m * 32 + mt * 16 + g + ch * 8;
            if (o < DD) {
                float bias = conv_b[o];
#pragma unroll
                for (int j = 0; j < 4; j++) {
#pragma unroll
                    for (int bb2 = 0; bb2 < 2; bb2++) {
                        int t = t0 + warp_n * 32 + j * 8 + q * 2 + bb2;
                        if (t < TP) {
                            float v = fmaxf(acc[mt][j][ch * 2 + bb2] + bias, 0.f);
                            __nv_bfloat16 h = __float2bfloat16(v);
                            size_t dst = ((size_t)b * TPAD + t) * DP + o;
                            g_Hthi[dst] = h;
                            g_Htlo[dst] = __float2bfloat16(v - __bfloat162float(h));
                        }
                    }
                }
            }
        }
    }
}

// ---------------------------------------------------------------------------
// Kernel 5: fused score-GEMM + online softmax, 3-stage pipeline
//   block: 128 l x 128 t-tile, 8 warps (4m x 2n, 32x64), 170 phases
// ---------------------------------------------------------------------------
__global__ void __launch_bounds__(256, 2) k_attn(const float* __restrict__ fc_bias,
                                                 float* __restrict__ out) {
    extern __shared__ __align__(16) char dynsm[];
    __shared__ float s_m[128];
    __shared__ float s_e[128];
    __shared__ float s_s[128];
    __shared__ float p_m[2][128];
    __shared__ float p_e[2][128];
    __shared__ float p_s[2][128];

    int l0 = blockIdx.x * 128;
    int b  = blockIdx.y;
    int tid = threadIdx.x;
    int lane = tid & 31;
    int warp = tid >> 5;
    int warp_m = warp >> 1;
    int warp_n = warp & 1;
    int g = lane >> 2;
    int q = lane & 3;

    if (tid < 128) {
        s_m[tid] = -INFINITY;
        s_e[tid] = 0.f;
        s_s[tid] = 0.f;
    }

    u32 smbase = smem_u32(dynsm);
    u32 x = (u32)(lane & 7);
    u32 c0a = (u32)(lane >> 4);
    u32 c0b = (u32)((lane >> 3) & 1);

    u32 rA[2];
#pragma unroll
    for (int mt = 0; mt < 2; mt++) {
        rA[mt] = (u32)((warp_m * 32 + mt * 16 + (lane & 15)) * 128);
    }
    u32 rB[4];
    {
        int brow = ((lane >> 4) & 1) * 8 + (lane & 7);
#pragma unroll
        for (int j2 = 0; j2 < 4; j2++) {
            rB[j2] = (u32)(A_SBB + (warp_n * 64 + j2 * 16 + brow) * 128);
        }
    }

    const __nv_bfloat16* BHbase = g_Hthi + (size_t)b * TPAD * DP;
    const __nv_bfloat16* BLbase = g_Htlo + (size_t)b * TPAD * DP;

    const int NPH = 170;

#pragma unroll 1
    for (int pre = 0; pre < 2; pre++) {
        int d0 = (pre % 10) * 32;
        stage_fill_a(smbase + (u32)(pre * A_STG), tid,
                     g_Uhi + (size_t)l0 * DP + d0,
                     g_Ulo + (size_t)l0 * DP + d0,
                     BHbase + d0,
                     BLbase + d0);
    }

    float acc[2][8][4];
    int slot = 0;
    int islot = 2;

#pragma unroll 1
    for (int p = 0; p < NPH; p++) {
        int tile = p / 10;
        int ph = p - tile * 10;

        if (ph == 0) {
#pragma unroll
            for (int mt = 0; mt < 2; mt++) {
#pragma unroll
                for (int j = 0; j < 8; j++) {
#pragma unroll
                    for (int c = 0; c < 4; c++) { acc[mt][j][c] = 0.f; }
                }
            }
        }

        if (p < NPH - 1) { cpa_wait1(); } else { cpa_wait0(); }
        __syncthreads();

        if (p + 2 < NPH) {
            int pn = p + 2;
            int tn = pn / 10;
            int d0 = (pn - tn * 10) * 32;
            int tt0 = tn * 128;
            stage_fill_a(smbase + (u32)(islot * A_STG), tid,
                         g_Uhi + (size_t)l0 * DP + d0,
                         g_Ulo + (size_t)l0 * DP + d0,
                         BHbase + (size_t)tt0 * DP + d0,
                         BLbase + (size_t)tt0 * DP + d0);
        }

        mma_phase_a(smbase + (u32)(slot * A_STG), rA, rB, x, c0a, c0b, acc);

        if (ph == 9) {
            int t0 = tile * 128;
#pragma unroll
            for (int mt = 0; mt < 2; mt++) {
#pragma unroll
                for (int ch = 0; ch < 2; ch++) {
                    int row = warp_m * 32 + mt * 16 + g + ch * 8;
                    float mx = -INFINITY;
                    float pe = 0.f;
                    float ps = 0.f;
                    if (tile < 16) {
                        // fast path: all 128 t-cols valid
#pragma unroll
                        for (int j = 0; j < 8; j++) {
#pragma unroll
                            for (int bb2 = 0; bb2 < 2; bb2++) {
                                mx = fmaxf(mx, acc[mt][j][ch * 2 + bb2]);
                            }
                        }
                        mx = fmaxf(mx, __shfl_xor_sync(0xffffffffu, mx, 1));
                        mx = fmaxf(mx, __shfl_xor_sync(0xffffffffu, mx, 2));
#pragma unroll
                        for (int j = 0; j < 8; j++) {
#pragma unroll
                            for (int bb2 = 0; bb2 < 2; bb2++) {
                                float v = acc[mt][j][ch * 2 + bb2];
                                float pv = __expf(v - mx);
                                pe += pv;
                                ps += pv * v;
                            }
                        }
                    } else {
                        // masked tail tile (t0 = 2048, valid t < 2057)
#pragma unroll
                        for (int j = 0; j < 8; j++) {
#pragma unroll
                            for (int bb2 = 0; bb2 < 2; bb2++) {
                                int t = t0 + warp_n * 64 + j * 8 + q * 2 + bb2;
                                if (t < TP) { mx = fmaxf(mx, acc[mt][j][ch * 2 + bb2]); }
                            }
                        }
                        mx = fmaxf(mx, __shfl_xor_sync(0xffffffffu, mx, 1));
                        mx = fmaxf(mx, __shfl_xor_sync(0xffffffffu, mx, 2));
#pragma unroll
                        for (int j = 0; j < 8; j++) {
#pragma unroll
                            for (int bb2 = 0; bb2 < 2; bb2++) {
                                int t = t0 + warp_n * 64 + j * 8 + q * 2 + bb2;
                                if (t < TP) {
                                    float v = acc[mt][j][ch * 2 + bb2];
                                    float pv = __expf(v - mx);
                                    pe += pv;
                                    ps += pv * v;
                                }
                            }
                        }
                    }
                    pe += __shfl_xor_sync(0xffffffffu, pe, 1);
                    ps += __shfl_xor_sync(0xffffffffu, ps, 1);
                    pe += __shfl_xor_sync(0xffffffffu, pe, 2);
                    ps += __shfl_xor_sync(0xffffffffu, ps, 2);

                    if (q == 0) {
                        p_m[warp_n][row] = mx;
                        p_e[warp_n][row] = pe;
                        p_s[warp_n][row] = ps;
                    }
                }
            }
            __syncthreads();

            if (tid < 128) {
                float mo = s_m[tid];
                float eo = s_e[tid];
                float so = s_s[tid];
#pragma unroll
                for (int pp = 0; pp < 2; pp++) {
                    float mxp = p_m[pp][tid];
                    float pep = p_e[pp][tid];
                    float psp = p_s[pp][tid];
                    float mn = fmaxf(mo, mxp);
                    float e1 = __expf(mo - mn);
                    float e2 = __expf(mxp - mn);
                    eo = eo * e1 + pep * e2;
                    so = so * e1 + psp * e2;
                    mo = mn;
                }
                s_m[tid] = mo;
                s_e[tid] = eo;
                s_s[tid] = so;
            }
        }

        slot++;
        if (slot == NSTG) { slot = 0; }
        islot++;
        if (islot == NSTG) { islot = 0; }
    }

    if (tid < 128) {
        int l = l0 + tid;
        if (l < LL) { out[b * LL + l] = s_s[tid] / s_e[tid] + fc_bias[l]; }
    }
}

// ---------------------------------------------------------------------------
// Launch
// ---------------------------------------------------------------------------
extern "C" void kernel_launch(void* const* d_in, const int* in_sizes, int n_in,
                              void* d_out, int out_size) {
    const int* ids = nullptr;
    const float* emb = nullptr;
    const float* cw = nullptr;
    const float* cb = nullptr;
    const float* U = nullptr;
    const float* fb = nullptr;
    for (int i = 0; i < n_in; i++) {
        int s = in_sizes[i];
        if (s == BB * TT) { ids = (const int*)d_in[i]; }
        else if (s == 50000 * DD) { emb = (const float*)d_in[i]; }
        else if (s == DD * DD * KK) { cw = (const float*)d_in[i]; }
        else if (s == DD) { cb = (const float*)d_in[i]; }
        else if (s == LL * DD) { U = (const float*)d_in[i]; }
        else if (s == LL) { fb = (const float*)d_in[i]; }
    }
    float* out = (float*)d_out;

    const int DYN_CONV = NSTG * C_STG;   // 73728
    const int DYN_ATTN = NSTG * A_STG;   // 98304
    cudaFuncSetAttribute(k_conv, cudaFuncAttributeMaxDynamicSharedMemorySize, DYN_CONV);
    cudaFuncSetAttribute(k_attn, cudaFuncAttributeMaxDynamicSharedMemorySize, DYN_ATTN);

    k_wsplit<<<(KK * DD * DD + 255) / 256, 256>>>(cw);
    k_usplit<<<(LL * DD + 255) / 256, 256>>>(U);
    k_gather<<<(BB * TT * DD + 255) / 256, 256>>>(ids, emb);
    k_conv<<<dim3(TPAD / 64, OP2 / 128, BB), 256, DYN_CONV>>>(cb);
    k_attn<<<dim3(LP / 128, BB), 256, DYN_ATTN>>>(fb, out);
}

// round 15
// speedup vs baseline: 1.2917x; 1.0144x over previous
#include <cuda_runtime.h>
#include <cuda_bf16.h>
#include <cstdint>
#include <math.h>

typedef unsigned int u32;

// Problem dims
#define BB   8
#define TT   2048
#define DD   300
#define KK   10
#define LL   8921
#define TP   2057     // TT + KK - 1
#define LP   8960     // L padded to 70*128
#define OP2  384      // o padded to 3*128
#define DP   320      // d padded to 20*16
#define TPAD 2176     // t' padded to 17*128 (attn tiling)
#define ETR  2208     // embed rows: 9 halo + 2048 + tail zeros

// Attn stage: A 128 rows (16KB) + B 128 rows (16KB); 3 stages
#define A_SBB  16384
#define A_STG  32768
// Conv stage: A 128 rows (16KB) + B 96 rows (12KB); 3 stages
#define C_SBB  16384
#define C_STG  28672
#define NSTG   3

// Scratch (device globals, zero-initialized; padding regions never written)
__device__ __align__(16) __nv_bfloat16 g_Ehi[BB * ETR * DP];   // [b][9+tau][d]
__device__ __align__(16) __nv_bfloat16 g_Elo[BB * ETR * DP];
__device__ __align__(16) __nv_bfloat16 g_Whi[KK * OP2 * DP];   // [k][o][i]
__device__ __align__(16) __nv_bfloat16 g_Wlo[KK * OP2 * DP];
__device__ __align__(16) __nv_bfloat16 g_Uhi[LP * DP];         // [l][d]
__device__ __align__(16) __nv_bfloat16 g_Ulo[LP * DP];
__device__ __align__(16) __nv_bfloat16 g_Hthi[BB * TPAD * DP]; // [b][t][o]
__device__ __align__(16) __nv_bfloat16 g_Htlo[BB * TPAD * DP];

// ---------------------------------------------------------------------------
// PTX helpers
// ---------------------------------------------------------------------------
__device__ __forceinline__ u32 smem_u32(const void* p) {
    return (u32)__cvta_generic_to_shared(p);
}

__device__ __forceinline__ void ldsm4(u32* r, u32 addr) {
    asm volatile("ldmatrix.sync.aligned.m8n8.x4.shared.b16 {%0,%1,%2,%3}, [%4];"
                 : "=r"(r[0]), "=r"(r[1]), "=r"(r[2]), "=r"(r[3])
                 : "r"(addr));
}

__device__ __forceinline__ void mma16816(float* d, const u32* a, const u32* b) {
    asm volatile(
        "mma.sync.aligned.m16n8k16.row.col.f32.bf16.bf16.f32 "
        "{%0,%1,%2,%3}, {%4,%5,%6,%7}, {%8,%9}, {%0,%1,%2,%3};"
        : "+f"(d[0]), "+f"(d[1]), "+f"(d[2]), "+f"(d[3])
        : "r"(a[0]), "r"(a[1]), "r"(a[2]), "r"(a[3]), "r"(b[0]), "r"(b[1]));
}

__device__ __forceinline__ void cpa16(u32 dst, const void* src) {
    asm volatile("cp.async.cg.shared.global [%0], [%1], 16;" :: "r"(dst), "l"(src));
}
__device__ __forceinline__ void cpa_commit() {
    asm volatile("cp.async.commit_group;");
}
__device__ __forceinline__ void cpa_wait1() {
    asm volatile("cp.async.wait_group 1;");
}
__device__ __forceinline__ void cpa_wait0() {
    asm volatile("cp.async.wait_group 0;");
}

// ---------------------------------------------------------------------------
// Kernel 1: embedding gather + bf16 hi/lo split -> Ehi/Elo[b][9+tau][d]
// ---------------------------------------------------------------------------
__global__ void k_gather(const int* __restrict__ ids, const float* __restrict__ emb) {
    int idx = blockIdx.x * 256 + threadIdx.x;
    if (idx >= BB * TT * DD) { return; }
    int d = idx % DD;
    int tok = idx / DD;
    int b = tok / TT;
    int tau = tok - b * TT;
    int row = ids[tok];
    float v = emb[row * DD + d];
    __nv_bfloat16 h = __float2bfloat16(v);
    size_t o = ((size_t)b * ETR + 9 + tau) * DP + d;
    g_Ehi[o] = h;
    g_Elo[o] = __float2bfloat16(v - __bfloat162float(h));
}

// ---------------------------------------------------------------------------
// Kernel 2: conv_w (O,I,K) fp32 -> Whi/Wlo[k][o][i]
// ---------------------------------------------------------------------------
__global__ void k_wsplit(const float* __restrict__ w) {
    int idx = blockIdx.x * 256 + threadIdx.x;
    if (idx >= KK * DD * DD) { return; }
    int i = idx % DD;
    int rem = idx / DD;
    int o = rem % DD;
    int k = rem / DD;
    float v = w[(o * DD + i) * KK + k];
    __nv_bfloat16 h = __float2bfloat16(v);
    size_t dst = ((size_t)k * OP2 + o) * DP + i;
    g_Whi[dst] = h;
    g_Wlo[dst] = __float2bfloat16(v - __bfloat162float(h));
}

// ---------------------------------------------------------------------------
// Kernel 3: U fp32 [l][d] -> bf16 hi/lo split [l][DP]
// ---------------------------------------------------------------------------
__global__ void k_usplit(const float* __restrict__ U) {
    int idx = blockIdx.x * 256 + threadIdx.x;
    if (idx >= LL * DD) { return; }
    int l = idx / DD;
    int d = idx - l * DD;
    float u = U[idx];
    __nv_bfloat16 h = __float2bfloat16(u);
    g_Uhi[l * DP + d] = h;
    g_Ulo[l * DP + d] = __float2bfloat16(u - __bfloat162float(h));
}

// ---------------------------------------------------------------------------
// Conv stage fill: A 128 rows, B 96 rows; chunk swizzle phys = c ^ (row&7)
// ---------------------------------------------------------------------------
__device__ __forceinline__ void stage_fill_c(u32 sb, int tid,
                                             const __nv_bfloat16* Ahi,
                                             const __nv_bfloat16* Alo,
                                             const __nv_bfloat16* Bhi,
                                             const __nv_bfloat16* Blo) {
#pragma unroll
    for (int it = 0; it < 4; it++) {
        int idx = tid + it * 256;
        int row = idx >> 3;
        int c = idx & 7;
        u32 dst = sb + (u32)(row * 128) + (u32)(((c ^ (row & 7)) << 4));
        size_t go = (size_t)row * DP + (c & 3) * 8;
        cpa16(dst, (c < 4) ? (Ahi + go) : (Alo + go));
    }
#pragma unroll
    for (int it = 0; it < 3; it++) {
        int idx = tid + it * 256;
        int row = idx >> 3;
        int c = idx & 7;
        u32 dst = sb + (u32)C_SBB + (u32)(row * 128) + (u32)(((c ^ (row & 7)) << 4));
        size_t go = (size_t)row * DP + (c & 3) * 8;
        cpa16(dst, (c < 4) ? (Bhi + go) : (Blo + go));
    }
    cpa_commit();
}

// ---------------------------------------------------------------------------
// Attn stage fill: A 128 rows, B 128 rows
// ---------------------------------------------------------------------------
__device__ __forceinline__ void stage_fill_a(u32 sb, int tid,
                                             const __nv_bfloat16* Ahi,
                                             const __nv_bfloat16* Alo,
                                             const __nv_bfloat16* Bhi,
                                             const __nv_bfloat16* Blo) {
#pragma unroll
    for (int it = 0; it < 8; it++) {
        int idx = tid + it * 256;
        int rem = idx & 1023;
        int row = rem >> 3;
        int c = rem & 7;
        u32 dst = sb + (u32)((it >> 2) * A_SBB) + (u32)(row * 128)
                + (u32)(((c ^ (row & 7)) << 4));
        size_t go = (size_t)row * DP + (c & 3) * 8;
        const __nv_bfloat16* src;
        if (it < 4) {
            src = (c < 4) ? (Ahi + go) : (Alo + go);
        } else {
            src = (c < 4) ? (Bhi + go) : (Blo + go);
        }
        cpa16(dst, src);
    }
    cpa_commit();
}

// ---------------------------------------------------------------------------
// Conv mma phase: warp tile 32x48 (2 m-frags, 3 B j2-frags, j 0..5)
// ---------------------------------------------------------------------------
__device__ __forceinline__ void mma_phase_c(u32 sb, const u32* rA, const u32* rB,
                                            u32 x, u32 c0a, u32 c0b,
                                            float acc[2][6][4]) {
#pragma unroll
    for (int kc = 0; kc < 2; kc++) {
        u32 ca = c0a + (u32)(kc * 2);
        u32 cb = c0b + (u32)(kc * 2);
        u32 ah0[4];
        u32 ah1[4];
        u32 al0[4];
        u32 al1[4];
        u32 bh[3][4];
        u32 bl[3][4];

        ldsm4(ah0, sb + rA[0] + ((ca ^ x) << 4));
        ldsm4(ah1, sb + rA[1] + ((ca ^ x) << 4));
#pragma unroll
        for (int j2 = 0; j2 < 3; j2++) {
            ldsm4(bh[j2], sb + rB[j2] + ((cb ^ x) << 4));
        }

#pragma unroll
        for (int j = 0; j < 6; j++) {
            const u32* bp = &bh[j >> 1][(j & 1) * 2];
            mma16816(acc[0][j], ah0, bp);
            mma16816(acc[1][j], ah1, bp);
        }

        ldsm4(al0, sb + rA[0] + (((ca + 4) ^ x) << 4));
        ldsm4(al1, sb + rA[1] + (((ca + 4) ^ x) << 4));
#pragma unroll
        for (int j = 0; j < 6; j++) {
            const u32* bp = &bh[j >> 1][(j & 1) * 2];
            mma16816(acc[0][j], al0, bp);
            mma16816(acc[1][j], al1, bp);
        }

#pragma unroll
        for (int j2 = 0; j2 < 3; j2++) {
            ldsm4(bl[j2], sb + rB[j2] + (((cb + 4) ^ x) << 4));
        }
#pragma unroll
        for (int j = 0; j < 6; j++) {
            const u32* bp = &bl[j >> 1][(j & 1) * 2];
            mma16816(acc[0][j], ah0, bp);
            mma16816(acc[1][j], ah1, bp);
        }
    }
}

// ---------------------------------------------------------------------------
// Attn mma phase: warp tile 32x64 (2 m-frags, 4 B j2-frags, j 0..7)
// ---------------------------------------------------------------------------
__device__ __forceinline__ void mma_phase_a(u32 sb, const u32* rA, const u32* rB,
                                            u32 x, u32 c0a, u32 c0b,
                                            float acc[2][8][4]) {
#pragma unroll
    for (int kc = 0; kc < 2; kc++) {
        u32 ca = c0a + (u32)(kc * 2);
        u32 cb = c0b + (u32)(kc * 2);
        u32 ah0[4];
        u32 ah1[4];
        u32 al0[4];
        u32 al1[4];
        u32 bh[4][4];
        u32 bl[4][4];

        ldsm4(ah0, sb + rA[0] + ((ca ^ x) << 4));
        ldsm4(ah1, sb + rA[1] + ((ca ^ x) << 4));
#pragma unroll
        for (int j2 = 0; j2 < 4; j2++) {
            ldsm4(bh[j2], sb + rB[j2] + ((cb ^ x) << 4));
        }

#pragma unroll
        for (int j = 0; j < 8; j++) {
            const u32* bp = &bh[j >> 1][(j & 1) * 2];
            mma16816(acc[0][j], ah0, bp);
            mma16816(acc[1][j], ah1, bp);
        }

        ldsm4(al0, sb + rA[0] + (((ca + 4) ^ x) << 4));
        ldsm4(al1, sb + rA[1] + (((ca + 4) ^ x) << 4));
#pragma unroll
        for (int j = 0; j < 8; j++) {
            const u32* bp = &bh[j >> 1][(j & 1) * 2];
            mma16816(acc[0][j], al0, bp);
            mma16816(acc[1][j], al1, bp);
        }

#pragma unroll
        for (int j2 = 0; j2 < 4; j2++) {
            ldsm4(bl[j2], sb + rB[j2] + (((cb + 4) ^ x) << 4));
        }
#pragma unroll
        for (int j = 0; j < 8; j++) {
            const u32* bp = &bl[j >> 1][(j & 1) * 2];
            mma16816(acc[0][j], ah0, bp);
            mma16816(acc[1][j], ah1, bp);
        }
    }
}

// ---------------------------------------------------------------------------
// Kernel 4: conv1d, block 128o x 96t (8 warps, 32x48 tiles), 3-stage pipeline
//   grid 22 x 3 x 8 = 528 blocks (quant 89%, duty ~88%)
// ---------------------------------------------------------------------------
__global__ void __launch_bounds__(256, 2) k_conv(const float* __restrict__ conv_b) {
    extern __shared__ __align__(16) char dynsm[];
    int t0 = blockIdx.x * 96;
    int o0 = blockIdx.y * 128;
    int b  = blockIdx.z;
    int tid = threadIdx.x;
    int lane = tid & 31;
    int warp = tid >> 5;
    int warp_m = warp >> 1;
    int warp_n = warp & 1;
    int g = lane >> 2;
    int q = lane & 3;

    u32 smbase = smem_u32(dynsm);
    u32 x = (u32)(lane & 7);
    u32 c0a = (u32)(lane >> 4);
    u32 c0b = (u32)((lane >> 3) & 1);

    u32 rA[2];
#pragma unroll
    for (int mt = 0; mt < 2; mt++) {
        rA[mt] = (u32)((warp_m * 32 + mt * 16 + (lane & 15)) * 128);
    }
    u32 rB[3];
    {
        int brow = ((lane >> 4) & 1) * 8 + (lane & 7);
#pragma unroll
        for (int j2 = 0; j2 < 3; j2++) {
            rB[j2] = (u32)(C_SBB + (warp_n * 48 + j2 * 16 + brow) * 128);
        }
    }

    float acc[2][6][4];
#pragma unroll
    for (int mt = 0; mt < 2; mt++) {
#pragma unroll
        for (int j = 0; j < 6; j++) {
#pragma unroll
            for (int c = 0; c < 4; c++) { acc[mt][j][c] = 0.f; }
        }
    }

    const int NPH = 100;

#pragma unroll 1
    for (int pre = 0; pre < 2; pre++) {
        int k = pre / 10;
        int d0 = (pre % 10) * 32;
        stage_fill_c(smbase + (u32)(pre * C_STG), tid,
                     g_Whi + ((size_t)k * OP2 + o0) * DP + d0,
                     g_Wlo + ((size_t)k * OP2 + o0) * DP + d0,
                     g_Ehi + ((size_t)b * ETR + t0 + k) * DP + d0,
                     g_Elo + ((size_t)b * ETR + t0 + k) * DP + d0);
    }

    int slot = 0;
    int islot = 2;
#pragma unroll 1
    for (int p = 0; p < NPH; p++) {
        if (p < NPH - 1) { cpa_wait1(); } else { cpa_wait0(); }
        __syncthreads();

        if (p + 2 < NPH) {
            int pn = p + 2;
            int k = pn / 10;
            int d0 = (pn - k * 10) * 32;
            stage_fill_c(smbase + (u32)(islot * C_STG), tid,
                         g_Whi + ((size_t)k * OP2 + o0) * DP + d0,
                         g_Wlo + ((size_t)k * OP2 + o0) * DP + d0,
                         g_Ehi + ((size_t)b * ETR + t0 + k) * DP + d0,
                         g_Elo + ((size_t)b * ETR + t0 + k) * DP + d0);
        }

        mma_phase_c(smbase + (u32)(slot * C_STG), rA, rB, x, c0a, c0b, acc);

        slot++;
        if (slot == NSTG) { slot = 0; }
        islot++;
        if (islot == NSTG) { islot = 0; }
    }

    // Epilogue: bias + relu, hi/lo split, transposed element stores to [t][o]
#pragma unroll
    for (int mt = 0; mt < 2; mt++) {
#pragma unroll
        for (int ch = 0; ch < 2; ch++) {
            int o = o0 + warp_m * 32 + mt * 16 + g + ch * 8;
            if (o < DD) {
                float bias = conv_b[o];
#pragma unroll
                for (int j = 0; j < 6; j++) {
#pragma unroll
                    for (int bb2 = 0; bb2 < 2; bb2++) {
                        int t = t0 + warp_n * 48 + j * 8 + q * 2 + bb2;
                        if (t < TP) {
                            float v = fmaxf(acc[mt][j][ch * 2 + bb2] + bias, 0.f);
                            __nv_bfloat16 h = __float2bfloat16(v);
                            size_t dst = ((size_t)b * TPAD + t) * DP + o;
                            g_Hthi[dst] = h;
                            g_Htlo[dst] = __float2bfloat16(v - __bfloat162float(h));
                        }
                    }
                }
            }
        }
    }
}

// ---------------------------------------------------------------------------
// Kernel 5: fused score-GEMM + online softmax, 3-stage pipeline
//   block: 128 l x 128 t-tile, 8 warps (4m x 2n, 32x64), 170 phases
// ---------------------------------------------------------------------------
__global__ void __launch_bounds__(256, 2) k_attn(const float* __restrict__ fc_bias,
                                                 float* __restrict__ out) {
    extern __shared__ __align__(16) char dynsm[];
    __shared__ float s_m[128];
    __shared__ float s_e[128];
    __shared__ float s_s[128];
    __shared__ float p_m[2][128];
    __shared__ float p_e[2][128];
    __shared__ float p_s[2][128];

    int l0 = blockIdx.x * 128;
    int b  = blockIdx.y;
    int tid = threadIdx.x;
    int lane = tid & 31;
    int warp = tid >> 5;
    int warp_m = warp >> 1;
    int warp_n = warp & 1;
    int g = lane >> 2;
    int q = lane & 3;

    if (tid < 128) {
        s_m[tid] = -INFINITY;
        s_e[tid] = 0.f;
        s_s[tid] = 0.f;
    }

    u32 smbase = smem_u32(dynsm);
    u32 x = (u32)(lane & 7);
    u32 c0a = (u32)(lane >> 4);
    u32 c0b = (u32)((lane >> 3) & 1);

    u32 rA[2];
#pragma unroll
    for (int mt = 0; mt < 2; mt++) {
        rA[mt] = (u32)((warp_m * 32 + mt * 16 + (lane & 15)) * 128);
    }
    u32 rB[4];
    {
        int brow = ((lane >> 4) & 1) * 8 + (lane & 7);
#pragma unroll
        for (int j2 = 0; j2 < 4; j2++) {
            rB[j2] = (u32)(A_SBB + (warp_n * 64 + j2 * 16 + brow) * 128);
        }
    }

    const __nv_bfloat16* BHbase = g_Hthi + (size_t)b * TPAD * DP;
    const __nv_bfloat16* BLbase = g_Htlo + (size_t)b * TPAD * DP;

    const int NPH = 170;

#pragma unroll 1
    for (int pre = 0; pre < 2; pre++) {
        int d0 = (pre % 10) * 32;
        stage_fill_a(smbase + (u32)(pre * A_STG), tid,
                     g_Uhi + (size_t)l0 * DP + d0,
                     g_Ulo + (size_t)l0 * DP + d0,
                     BHbase + d0,
                     BLbase + d0);
    }

    float acc[2][8][4];
    int slot = 0;
    int islot = 2;

#pragma unroll 1
    for (int p = 0; p < NPH; p++) {
        int tile = p / 10;
        int ph = p - tile * 10;

        if (ph == 0) {
#pragma unroll
            for (int mt = 0; mt < 2; mt++) {
#pragma unroll
                for (int j = 0; j < 8; j++) {
#pragma unroll
                    for (int c = 0; c < 4; c++) { acc[mt][j][c] = 0.f; }
                }
            }
        }

        if (p < NPH - 1) { cpa_wait1(); } else { cpa_wait0(); }
        __syncthreads();

        if (p + 2 < NPH) {
            int pn = p + 2;
            int tn = pn / 10;
            int d0 = (pn - tn * 10) * 32;
            int tt0 = tn * 128;
            stage_fill_a(smbase + (u32)(islot * A_STG), tid,
                         g_Uhi + (size_t)l0 * DP + d0,
                         g_Ulo + (size_t)l0 * DP + d0,
                         BHbase + (size_t)tt0 * DP + d0,
                         BLbase + (size_t)tt0 * DP + d0);
        }

        mma_phase_a(smbase + (u32)(slot * A_STG), rA, rB, x, c0a, c0b, acc);

        if (ph == 9) {
            int t0 = tile * 128;
#pragma unroll
            for (int mt = 0; mt < 2; mt++) {
#pragma unroll
                for (int ch = 0; ch < 2; ch++) {
                    int row = warp_m * 32 + mt * 16 + g + ch * 8;
                    float mx = -INFINITY;
                    float pe = 0.f;
                    float ps = 0.f;
                    if (tile < 16) {
                        // fast path: all 128 t-cols valid
#pragma unroll
                        for (int j = 0; j < 8; j++) {
#pragma unroll
                            for (int bb2 = 0; bb2 < 2; bb2++) {
                                mx = fmaxf(mx, acc[mt][j][ch * 2 + bb2]);
                            }
                        }
                        mx = fmaxf(mx, __shfl_xor_sync(0xffffffffu, mx, 1));
                        mx = fmaxf(mx, __shfl_xor_sync(0xffffffffu, mx, 2));
#pragma unroll
                        for (int j = 0; j < 8; j++) {
#pragma unroll
                            for (int bb2 = 0; bb2 < 2; bb2++) {
                                float v = acc[mt][j][ch * 2 + bb2];
                                float pv = __expf(v - mx);
                                pe += pv;
                                ps += pv * v;
                            }
                        }
                    } else {
                        // masked tail tile (t0 = 2048, valid t < 2057)
#pragma unroll
                        for (int j = 0; j < 8; j++) {
#pragma unroll
                            for (int bb2 = 0; bb2 < 2; bb2++) {
                                int t = t0 + warp_n * 64 + j * 8 + q * 2 + bb2;
                                if (t < TP) { mx = fmaxf(mx, acc[mt][j][ch * 2 + bb2]); }
                            }
                        }
                        mx = fmaxf(mx, __shfl_xor_sync(0xffffffffu, mx, 1));
                        mx = fmaxf(mx, __shfl_xor_sync(0xffffffffu, mx, 2));
#pragma unroll
                        for (int j = 0; j < 8; j++) {
#pragma unroll
                            for (int bb2 = 0; bb2 < 2; bb2++) {
                                int t = t0 + warp_n * 64 + j * 8 + q * 2 + bb2;
                                if (t < TP) {
                                    float v = acc[mt][j][ch * 2 + bb2];
                                    float pv = __expf(v - mx);
                                    pe += pv;
                                    ps += pv * v;
                                }
                            }
                        }
                    }
                    pe += __shfl_xor_sync(0xffffffffu, pe, 1);
                    ps += __shfl_xor_sync(0xffffffffu, ps, 1);
                    pe += __shfl_xor_sync(0xffffffffu, pe, 2);
                    ps += __shfl_xor_sync(0xffffffffu, ps, 2);

                    if (q == 0) {
                        p_m[warp_n][row] = mx;
                        p_e[warp_n][row] = pe;
                        p_s[warp_n][row] = ps;
                    }
                }
            }
            __syncthreads();

            if (tid < 128) {
                float mo = s_m[tid];
                float eo = s_e[tid];
                float so = s_s[tid];
#pragma unroll
                for (int pp = 0; pp < 2; pp++) {
                    float mxp = p_m[pp][tid];
                    float pep = p_e[pp][tid];
                    float psp = p_s[pp][tid];
                    float mn = fmaxf(mo, mxp);
                    float e1 = __expf(mo - mn);
                    float e2 = __expf(mxp - mn);
                    eo = eo * e1 + pep * e2;
                    so = so * e1 + psp * e2;
                    mo = mn;
                }
                s_m[tid] = mo;
                s_e[tid] = eo;
                s_s[tid] = so;
            }
        }

        slot++;
        if (slot == NSTG) { slot = 0; }
        islot++;
        if (islot == NSTG) { islot = 0; }
    }

    if (tid < 128) {
        int l = l0 + tid;
        if (l < LL) { out[b * LL + l] = s_s[tid] / s_e[tid] + fc_bias[l]; }
    }
}

// ---------------------------------------------------------------------------
// Launch
// ---------------------------------------------------------------------------
extern "C" void kernel_launch(void* const* d_in, const int* in_sizes, int n_in,
                              void* d_out, int out_size) {
    const int* ids = nullptr;
    const float* emb = nullptr;
    const float* cw = nullptr;
    const float* cb = nullptr;
    const float* U = nullptr;
    const float* fb = nullptr;
    for (int i = 0; i < n_in; i++) {
        int s = in_sizes[i];
        if (s == BB * TT) { ids = (const int*)d_in[i]; }
        else if (s == 50000 * DD) { emb = (const float*)d_in[i]; }
        else if (s == DD * DD * KK) { cw = (const float*)d_in[i]; }
        else if (s == DD) { cb = (const float*)d_in[i]; }
        else if (s == LL * DD) { U = (const float*)d_in[i]; }
        else if (s == LL) { fb = (const float*)d_in[i]; }
    }
    float* out = (float*)d_out;

    const int DYN_CONV = NSTG * C_STG;   // 86016
    const int DYN_ATTN = NSTG * A_STG;   // 98304
    cudaFuncSetAttribute(k_conv, cudaFuncAttributeMaxDynamicSharedMemorySize, DYN_CONV);
    cudaFuncSetAttribute(k_attn, cudaFuncAttributeMaxDynamicSharedMemorySize, DYN_ATTN);

    k_wsplit<<<(KK * DD * DD + 255) / 256, 256>>>(cw);
    k_usplit<<<(LL * DD + 255) / 256, 256>>>(U);
    k_gather<<<(BB * TT * DD + 255) / 256, 256>>>(ids, emb);
    k_conv<<<dim3((TP + 95) / 96, OP2 / 128, BB), 256, DYN_CONV>>>(cb);
    k_attn<<<dim3(LP / 128, BB), 256, DYN_ATTN>>>(fb, out);
}

// round 16
// speedup vs baseline: 1.6430x; 1.2719x over previous
#include <cuda_runtime.h>
#include <cuda_bf16.h>
#include <cuda_fp16.h>
#include <cstdint>
#include <math.h>

typedef unsigned int u32;

// Problem dims
#define BB   8
#define TT   2048
#define DD   300
#define KK   10
#define LL   8921
#define TP   2057     // TT + KK - 1
#define LP   8960     // L padded to 70*128
#define OP2  384      // o padded to 3*128
#define DP   320      // d padded to 20*16
#define TPAD 2176     // t' padded to 17*128 (attn tiling)
#define ETR  2208     // embed rows: 9 halo + 2048 + tail zeros

// Attn stage: A (U hi+lo fp16) 128 rows x 128B = 16KB; B (h hi fp16) 128 rows x 64B = 8KB
#define A_SBB  16384
#define A_STG  24576
// Conv stage: A 128 rows (16KB) + B 96 rows (12KB); 3 stages
#define C_SBB  16384
#define C_STG  28672
#define NSTG   3

// Scratch (device globals, zero-initialized; padding regions never written)
__device__ __align__(16) __nv_bfloat16 g_Ehi[BB * ETR * DP];   // [b][9+tau][d]
__device__ __align__(16) __nv_bfloat16 g_Elo[BB * ETR * DP];
__device__ __align__(16) __nv_bfloat16 g_Whi[KK * OP2 * DP];   // [k][o][i]
__device__ __align__(16) __nv_bfloat16 g_Wlo[KK * OP2 * DP];
__device__ __align__(16) __half g_Uhi[LP * DP];                // [l][d] fp16
__device__ __align__(16) __half g_Ulo[LP * DP];
__device__ __align__(16) __half g_Hthi[BB * TPAD * DP];        // [b][t][o] fp16 (hi only)

// ---------------------------------------------------------------------------
// PTX helpers
// ---------------------------------------------------------------------------
__device__ __forceinline__ u32 smem_u32(const void* p) {
    return (u32)__cvta_generic_to_shared(p);
}

__device__ __forceinline__ void ldsm4(u32* r, u32 addr) {
    asm volatile("ldmatrix.sync.aligned.m8n8.x4.shared.b16 {%0,%1,%2,%3}, [%4];"
                 : "=r"(r[0]), "=r"(r[1]), "=r"(r[2]), "=r"(r[3])
                 : "r"(addr));
}

__device__ __forceinline__ void mma16816(float* d, const u32* a, const u32* b) {
    asm volatile(
        "mma.sync.aligned.m16n8k16.row.col.f32.bf16.bf16.f32 "
        "{%0,%1,%2,%3}, {%4,%5,%6,%7}, {%8,%9}, {%0,%1,%2,%3};"
        : "+f"(d[0]), "+f"(d[1]), "+f"(d[2]), "+f"(d[3])
        : "r"(a[0]), "r"(a[1]), "r"(a[2]), "r"(a[3]), "r"(b[0]), "r"(b[1]));
}

__device__ __forceinline__ void mma16816h(float* d, const u32* a, const u32* b) {
    asm volatile(
        "mma.sync.aligned.m16n8k16.row.col.f32.f16.f16.f32 "
        "{%0,%1,%2,%3}, {%4,%5,%6,%7}, {%8,%9}, {%0,%1,%2,%3};"
        : "+f"(d[0]), "+f"(d[1]), "+f"(d[2]), "+f"(d[3])
        : "r"(a[0]), "r"(a[1]), "r"(a[2]), "r"(a[3]), "r"(b[0]), "r"(b[1]));
}

__device__ __forceinline__ void cpa16(u32 dst, const void* src) {
    asm volatile("cp.async.cg.shared.global [%0], [%1], 16;" :: "r"(dst), "l"(src));
}
__device__ __forceinline__ void cpa_commit() {
    asm volatile("cp.async.commit_group;");
}
__device__ __forceinline__ void cpa_wait1() {
    asm volatile("cp.async.wait_group 1;");
}
__device__ __forceinline__ void cpa_wait0() {
    asm volatile("cp.async.wait_group 0;");
}

// ---------------------------------------------------------------------------
// Kernel 1: embedding gather + bf16 hi/lo split -> Ehi/Elo[b][9+tau][d]
// ---------------------------------------------------------------------------
__global__ void k_gather(const int* __restrict__ ids, const float* __restrict__ emb) {
    int idx = blockIdx.x * 256 + threadIdx.x;
    if (idx >= BB * TT * DD) { return; }
    int d = idx % DD;
    int tok = idx / DD;
    int b = tok / TT;
    int tau = tok - b * TT;
    int row = ids[tok];
    float v = emb[row * DD + d];
    __nv_bfloat16 h = __float2bfloat16(v);
    size_t o = ((size_t)b * ETR + 9 + tau) * DP + d;
    g_Ehi[o] = h;
    g_Elo[o] = __float2bfloat16(v - __bfloat162float(h));
}

// ---------------------------------------------------------------------------
// Kernel 2: conv_w (O,I,K) fp32 -> Whi/Wlo[k][o][i]
// ---------------------------------------------------------------------------
__global__ void k_wsplit(const float* __restrict__ w) {
    int idx = blockIdx.x * 256 + threadIdx.x;
    if (idx >= KK * DD * DD) { return; }
    int i = idx % DD;
    int rem = idx / DD;
    int o = rem % DD;
    int k = rem / DD;
    float v = w[(o * DD + i) * KK + k];
    __nv_bfloat16 h = __float2bfloat16(v);
    size_t dst = ((size_t)k * OP2 + o) * DP + i;
    g_Whi[dst] = h;
    g_Wlo[dst] = __float2bfloat16(v - __bfloat162float(h));
}

// ---------------------------------------------------------------------------
// Kernel 3: U fp32 [l][d] -> fp16 hi/lo split [l][DP]
// ---------------------------------------------------------------------------
__global__ void k_usplit(const float* __restrict__ U) {
    int idx = blockIdx.x * 256 + threadIdx.x;
    if (idx >= LL * DD) { return; }
    int l = idx / DD;
    int d = idx - l * DD;
    float u = U[idx];
    __half h = __float2half_rn(u);
    g_Uhi[l * DP + d] = h;
    g_Ulo[l * DP + d] = __float2half_rn(u - __half2float(h));
}

// ---------------------------------------------------------------------------
// Conv stage fill: A 128 rows, B 96 rows; chunk swizzle phys = c ^ (row&7)
// ---------------------------------------------------------------------------
__device__ __forceinline__ void stage_fill_c(u32 sb, int tid,
                                             const __nv_bfloat16* Ahi,
                                             const __nv_bfloat16* Alo,
                                             const __nv_bfloat16* Bhi,
                                             const __nv_bfloat16* Blo) {
#pragma unroll
    for (int it = 0; it < 4; it++) {
        int idx = tid + it * 256;
        int row = idx >> 3;
        int c = idx & 7;
        u32 dst = sb + (u32)(row * 128) + (u32)(((c ^ (row & 7)) << 4));
        size_t go = (size_t)row * DP + (c & 3) * 8;
        cpa16(dst, (c < 4) ? (Ahi + go) : (Alo + go));
    }
#pragma unroll
    for (int it = 0; it < 3; it++) {
        int idx = tid + it * 256;
        int row = idx >> 3;
        int c = idx & 7;
        u32 dst = sb + (u32)C_SBB + (u32)(row * 128) + (u32)(((c ^ (row & 7)) << 4));
        size_t go = (size_t)row * DP + (c & 3) * 8;
        cpa16(dst, (c < 4) ? (Bhi + go) : (Blo + go));
    }
    cpa_commit();
}

// ---------------------------------------------------------------------------
// Attn stage fill: A (U hi/lo, 128 rows x 128B, phys = c^(row&7));
//                  B (h hi, 128 rows x 64B, phys = c^((row>>1)&3))
// ---------------------------------------------------------------------------
__device__ __forceinline__ void stage_fill_a(u32 sb, int tid,
                                             const __half* Ahi,
                                             const __half* Alo,
                                             const __half* Bhi) {
#pragma unroll
    for (int it = 0; it < 4; it++) {
        int idx = tid + it * 256;
        int row = idx >> 3;
        int c = idx & 7;
        u32 dst = sb + (u32)(row * 128) + (u32)(((c ^ (row & 7)) << 4));
        size_t go = (size_t)row * DP + (c & 3) * 8;
        cpa16(dst, (c < 4) ? (Ahi + go) : (Alo + go));
    }
#pragma unroll
    for (int it = 0; it < 2; it++) {
        int idx = tid + it * 256;
        int row = idx >> 2;
        int c = idx & 3;
        u32 dst = sb + (u32)A_SBB + (u32)(row * 64)
                + (u32)(((c ^ ((row >> 1) & 3)) << 4));
        size_t go = (size_t)row * DP + c * 8;
        cpa16(dst, Bhi + go);
    }
    cpa_commit();
}

// ---------------------------------------------------------------------------
// Conv mma phase: warp tile 32x48 (2 m-frags, 3 B j2-frags, j 0..5), bf16 3-pass
// ---------------------------------------------------------------------------
__device__ __forceinline__ void mma_phase_c(u32 sb, const u32* rA, const u32* rB,
                                            u32 x, u32 c0a, u32 c0b,
                                            float acc[2][6][4]) {
#pragma unroll
    for (int kc = 0; kc < 2; kc++) {
        u32 ca = c0a + (u32)(kc * 2);
        u32 cb = c0b + (u32)(kc * 2);
        u32 ah0[4];
        u32 ah1[4];
        u32 al0[4];
        u32 al1[4];
        u32 bh[3][4];
        u32 bl[3][4];

        ldsm4(ah0, sb + rA[0] + ((ca ^ x) << 4));
        ldsm4(ah1, sb + rA[1] + ((ca ^ x) << 4));
#pragma unroll
        for (int j2 = 0; j2 < 3; j2++) {
            ldsm4(bh[j2], sb + rB[j2] + ((cb ^ x) << 4));
        }

#pragma unroll
        for (int j = 0; j < 6; j++) {
            const u32* bp = &bh[j >> 1][(j & 1) * 2];
            mma16816(acc[0][j], ah0, bp);
            mma16816(acc[1][j], ah1, bp);
        }

        ldsm4(al0, sb + rA[0] + (((ca + 4) ^ x) << 4));
        ldsm4(al1, sb + rA[1] + (((ca + 4) ^ x) << 4));
#pragma unroll
        for (int j = 0; j < 6; j++) {
            const u32* bp = &bh[j >> 1][(j & 1) * 2];
            mma16816(acc[0][j], al0, bp);
            mma16816(acc[1][j], al1, bp);
        }

#pragma unroll
        for (int j2 = 0; j2 < 3; j2++) {
            ldsm4(bl[j2], sb + rB[j2] + (((cb + 4) ^ x) << 4));
        }
#pragma unroll
        for (int j = 0; j < 6; j++) {
            const u32* bp = &bl[j >> 1][(j & 1) * 2];
            mma16816(acc[0][j], ah0, bp);
            mma16816(acc[1][j], ah1, bp);
        }
    }
}

// ---------------------------------------------------------------------------
// Attn mma phase: fp16 2-pass (hi*hi + lo*hi), warp tile 32x64
//   A from 128B rows (xa = lane&7); B from 64B rows (xb = (lane>>1)&3)
// ---------------------------------------------------------------------------
__device__ __forceinline__ void mma_phase_a(u32 sb, const u32* rA, const u32* rB,
                                            u32 xa, u32 c0a, u32 xb, u32 c0b,
                                            float acc[2][8][4]) {
#pragma unroll
    for (int kc = 0; kc < 2; kc++) {
        u32 ca = c0a + (u32)(kc * 2);
        u32 cb = c0b + (u32)(kc * 2);
        u32 ah0[4];
        u32 ah1[4];
        u32 al0[4];
        u32 al1[4];
        u32 bh[4][4];

        ldsm4(ah0, sb + rA[0] + ((ca ^ xa) << 4));
        ldsm4(ah1, sb + rA[1] + ((ca ^ xa) << 4));
#pragma unroll
        for (int j2 = 0; j2 < 4; j2++) {
            ldsm4(bh[j2], sb + rB[j2] + ((cb ^ xb) << 4));
        }

        // pass 1: U_hi * h_hi
#pragma unroll
        for (int j = 0; j < 8; j++) {
            const u32* bp = &bh[j >> 1][(j & 1) * 2];
            mma16816h(acc[0][j], ah0, bp);
            mma16816h(acc[1][j], ah1, bp);
        }

        // pass 2: U_lo * h_hi
        ldsm4(al0, sb + rA[0] + (((ca + 4) ^ xa) << 4));
        ldsm4(al1, sb + rA[1] + (((ca + 4) ^ xa) << 4));
#pragma unroll
        for (int j = 0; j < 8; j++) {
            const u32* bp = &bh[j >> 1][(j & 1) * 2];
            mma16816h(acc[0][j], al0, bp);
            mma16816h(acc[1][j], al1, bp);
        }
    }
}

// ---------------------------------------------------------------------------
// Kernel 4: conv1d, block 128o x 96t (8 warps, 32x48 tiles), 3-stage pipeline
// ---------------------------------------------------------------------------
__global__ void __launch_bounds__(256, 2) k_conv(const float* __restrict__ conv_b) {
    extern __shared__ __align__(16) char dynsm[];
    int t0 = blockIdx.x * 96;
    int o0 = blockIdx.y * 128;
    int b  = blockIdx.z;
    int tid = threadIdx.x;
    int lane = tid & 31;
    int warp = tid >> 5;
    int warp_m = warp >> 1;
    int warp_n = warp & 1;
    int g = lane >> 2;
    int q = lane & 3;

    u32 smbase = smem_u32(dynsm);
    u32 x = (u32)(lane & 7);
    u32 c0a = (u32)(lane >> 4);
    u32 c0b = (u32)((lane >> 3) & 1);

    u32 rA[2];
#pragma unroll
    for (int mt = 0; mt < 2; mt++) {
        rA[mt] = (u32)((warp_m * 32 + mt * 16 + (lane & 15)) * 128);
    }
    u32 rB[3];
    {
        int brow = ((lane >> 4) & 1) * 8 + (lane & 7);
#pragma unroll
        for (int j2 = 0; j2 < 3; j2++) {
            rB[j2] = (u32)(C_SBB + (warp_n * 48 + j2 * 16 + brow) * 128);
        }
    }

    float acc[2][6][4];
#pragma unroll
    for (int mt = 0; mt < 2; mt++) {
#pragma unroll
        for (int j = 0; j < 6; j++) {
#pragma unroll
            for (int c = 0; c < 4; c++) { acc[mt][j][c] = 0.f; }
        }
    }

    const int NPH = 100;

#pragma unroll 1
    for (int pre = 0; pre < 2; pre++) {
        int k = pre / 10;
        int d0 = (pre % 10) * 32;
        stage_fill_c(smbase + (u32)(pre * C_STG), tid,
                     g_Whi + ((size_t)k * OP2 + o0) * DP + d0,
                     g_Wlo + ((size_t)k * OP2 + o0) * DP + d0,
                     g_Ehi + ((size_t)b * ETR + t0 + k) * DP + d0,
                     g_Elo + ((size_t)b * ETR + t0 + k) * DP + d0);
    }

    int slot = 0;
    int islot = 2;
#pragma unroll 1
    for (int p = 0; p < NPH; p++) {
        if (p < NPH - 1) { cpa_wait1(); } else { cpa_wait0(); }
        __syncthreads();

        if (p + 2 < NPH) {
            int pn = p + 2;
            int k = pn / 10;
            int d0 = (pn - k * 10) * 32;
            stage_fill_c(smbase + (u32)(islot * C_STG), tid,
                         g_Whi + ((size_t)k * OP2 + o0) * DP + d0,
                         g_Wlo + ((size_t)k * OP2 + o0) * DP + d0,
                         g_Ehi + ((size_t)b * ETR + t0 + k) * DP + d0,
                         g_Elo + ((size_t)b * ETR + t0 + k) * DP + d0);
        }

        mma_phase_c(smbase + (u32)(slot * C_STG), rA, rB, x, c0a, c0b, acc);

        slot++;
        if (slot == NSTG) { slot = 0; }
        islot++;
        if (islot == NSTG) { islot = 0; }
    }

    // Epilogue: bias + relu, fp16 store transposed to [t][o] (hi only)
#pragma unroll
    for (int mt = 0; mt < 2; mt++) {
#pragma unroll
        for (int ch = 0; ch < 2; ch++) {
            int o = o0 + warp_m * 32 + mt * 16 + g + ch * 8;
            if (o < DD) {
                float bias = conv_b[o];
#pragma unroll
                for (int j = 0; j < 6; j++) {
#pragma unroll
                    for (int bb2 = 0; bb2 < 2; bb2++) {
                        int t = t0 + warp_n * 48 + j * 8 + q * 2 + bb2;
                        if (t < TP) {
                            float v = fmaxf(acc[mt][j][ch * 2 + bb2] + bias, 0.f);
                            size_t dst = ((size_t)b * TPAD + t) * DP + o;
                            g_Hthi[dst] = __float2half_rn(v);
                        }
                    }
                }
            }
        }
    }
}

// ---------------------------------------------------------------------------
// Kernel 5: fused score-GEMM (fp16 2-pass) + online softmax, 3-stage pipeline
//   block: 128 l x 128 t-tile, 8 warps (4m x 2n, 32x64), 170 phases
// ---------------------------------------------------------------------------
__global__ void __launch_bounds__(256, 2) k_attn(const float* __restrict__ fc_bias,
                                                 float* __restrict__ out) {
    extern __shared__ __align__(16) char dynsm[];
    __shared__ float s_m[128];
    __shared__ float s_e[128];
    __shared__ float s_s[128];
    __shared__ float p_m[2][128];
    __shared__ float p_e[2][128];
    __shared__ float p_s[2][128];

    int l0 = blockIdx.x * 128;
    int b  = blockIdx.y;
    int tid = threadIdx.x;
    int lane = tid & 31;
    int warp = tid >> 5;
    int warp_m = warp >> 1;
    int warp_n = warp & 1;
    int g = lane >> 2;
    int q = lane & 3;

    if (tid < 128) {
        s_m[tid] = -INFINITY;
        s_e[tid] = 0.f;
        s_s[tid] = 0.f;
    }

    u32 smbase = smem_u32(dynsm);
    u32 xa = (u32)(lane & 7);
    u32 c0a = (u32)(lane >> 4);
    u32 xb = (u32)((lane >> 1) & 3);
    u32 c0b = (u32)((lane >> 3) & 1);

    u32 rA[2];
#pragma unroll
    for (int mt = 0; mt < 2; mt++) {
        rA[mt] = (u32)((warp_m * 32 + mt * 16 + (lane & 15)) * 128);
    }
    u32 rB[4];
    {
        int brow = ((lane >> 4) & 1) * 8 + (lane & 7);
#pragma unroll
        for (int j2 = 0; j2 < 4; j2++) {
            rB[j2] = (u32)(A_SBB + (warp_n * 64 + j2 * 16 + brow) * 64);
        }
    }

    const __half* BHbase = g_Hthi + (size_t)b * TPAD * DP;

    const int NPH = 170;

#pragma unroll 1
    for (int pre = 0; pre < 2; pre++) {
        int d0 = (pre % 10) * 32;
        stage_fill_a(smbase + (u32)(pre * A_STG), tid,
                     g_Uhi + (size_t)l0 * DP + d0,
                     g_Ulo + (size_t)l0 * DP + d0,
                     BHbase + d0);
    }

    float acc[2][8][4];
    int slot = 0;
    int islot = 2;

#pragma unroll 1
    for (int p = 0; p < NPH; p++) {
        int tile = p / 10;
        int ph = p - tile * 10;

        if (ph == 0) {
#pragma unroll
            for (int mt = 0; mt < 2; mt++) {
#pragma unroll
                for (int j = 0; j < 8; j++) {
#pragma unroll
                    for (int c = 0; c < 4; c++) { acc[mt][j][c] = 0.f; }
                }
            }
        }

        if (p < NPH - 1) { cpa_wait1(); } else { cpa_wait0(); }
        __syncthreads();

        if (p + 2 < NPH) {
            int pn = p + 2;
            int tn = pn / 10;
            int d0 = (pn - tn * 10) * 32;
            int tt0 = tn * 128;
            stage_fill_a(smbase + (u32)(islot * A_STG), tid,
                         g_Uhi + (size_t)l0 * DP + d0,
                         g_Ulo + (size_t)l0 * DP + d0,
                         BHbase + (size_t)tt0 * DP + d0);
        }

        mma_phase_a(smbase + (u32)(slot * A_STG), rA, rB, xa, c0a, xb, c0b, acc);

        if (ph == 9) {
            int t0 = tile * 128;
#pragma unroll
            for (int mt = 0; mt < 2; mt++) {
#pragma unroll
                for (int ch = 0; ch < 2; ch++) {
                    int row = warp_m * 32 + mt * 16 + g + ch * 8;
                    float mx = -INFINITY;
                    float pe = 0.f;
                    float ps = 0.f;
                    if (tile < 16) {
                        // fast path: all 128 t-cols valid
#pragma unroll
                        for (int j = 0; j < 8; j++) {
#pragma unroll
                            for (int bb2 = 0; bb2 < 2; bb2++) {
                                mx = fmaxf(mx, acc[mt][j][ch * 2 + bb2]);
                            }
                        }
                        mx = fmaxf(mx, __shfl_xor_sync(0xffffffffu, mx, 1));
                        mx = fmaxf(mx, __shfl_xor_sync(0xffffffffu, mx, 2));
#pragma unroll
                        for (int j = 0; j < 8; j++) {
#pragma unroll
                            for (int bb2 = 0; bb2 < 2; bb2++) {
                                float v = acc[mt][j][ch * 2 + bb2];
                                float pv = __expf(v - mx);
                                pe += pv;
                                ps += pv * v;
                            }
                        }
                    } else {
                        // masked tail tile (t0 = 2048, valid t < 2057)
#pragma unroll
                        for (int j = 0; j < 8; j++) {
#pragma unroll
                            for (int bb2 = 0; bb2 < 2; bb2++) {
                                int t = t0 + warp_n * 64 + j * 8 + q * 2 + bb2;
                                if (t < TP) { mx = fmaxf(mx, acc[mt][j][ch * 2 + bb2]); }
                            }
                        }
                        mx = fmaxf(mx, __shfl_xor_sync(0xffffffffu, mx, 1));
                        mx = fmaxf(mx, __shfl_xor_sync(0xffffffffu, mx, 2));
#pragma unroll
                        for (int j = 0; j < 8; j++) {
#pragma unroll
                            for (int bb2 = 0; bb2 < 2; bb2++) {
                                int t = t0 + warp_n * 64 + j * 8 + q * 2 + bb2;
                                if (t < TP) {
                                    float v = acc[mt][j][ch * 2 + bb2];
                                    float pv = __expf(v - mx);
                                    pe += pv;
                                    ps += pv * v;
                                }
                            }
                        }
                    }
                    pe += __shfl_xor_sync(0xffffffffu, pe, 1);
                    ps += __shfl_xor_sync(0xffffffffu, ps, 1);
                    pe += __shfl_xor_sync(0xffffffffu, pe, 2);
                    ps += __shfl_xor_sync(0xffffffffu, ps, 2);

                    if (q == 0) {
                        p_m[warp_n][row] = mx;
                        p_e[warp_n][row] = pe;
                        p_s[warp_n][row] = ps;
                    }
                }
            }
            __syncthreads();

            if (tid < 128) {
                float mo = s_m[tid];
                float eo = s_e[tid];
                float so = s_s[tid];
#pragma unroll
                for (int pp = 0; pp < 2; pp++) {
                    float mxp = p_m[pp][tid];
                    float pep = p_e[pp][tid];
                    float psp = p_s[pp][tid];
                    float mn = fmaxf(mo, mxp);
                    float e1 = __expf(mo - mn);
                    float e2 = __expf(mxp - mn);
                    eo = eo * e1 + pep * e2;
                    so = so * e1 + psp * e2;
                    mo = mn;
                }
                s_m[tid] = mo;
                s_e[tid] = eo;
                s_s[tid] = so;
            }
        }

        slot++;
        if (slot == NSTG) { slot = 0; }
        islot++;
        if (islot == NSTG) { islot = 0; }
    }

    if (tid < 128) {
        int l = l0 + tid;
        if (l < LL) { out[b * LL + l] = s_s[tid] / s_e[tid] + fc_bias[l]; }
    }
}

// ---------------------------------------------------------------------------
// Launch
// ---------------------------------------------------------------------------
extern "C" void kernel_launch(void* const* d_in, const int* in_sizes, int n_in,
                              void* d_out, int out_size) {
    const int* ids = nullptr;
    const float* emb = nullptr;
    const float* cw = nullptr;
    const float* cb = nullptr;
    const float* U = nullptr;
    const float* fb = nullptr;
    for (int i = 0; i < n_in; i++) {
        int s = in_sizes[i];
        if (s == BB * TT) { ids = (const int*)d_in[i]; }
        else if (s == 50000 * DD) { emb = (const float*)d_in[i]; }
        else if (s == DD * DD * KK) { cw = (const float*)d_in[i]; }
        else if (s == DD) { cb = (const float*)d_in[i]; }
        else if (s == LL * DD) { U = (const float*)d_in[i]; }
        else if (s == LL) { fb = (const float*)d_in[i]; }
    }
    float* out = (float*)d_out;

    const int DYN_CONV = NSTG * C_STG;   // 86016
    const int DYN_ATTN = NSTG * A_STG;   // 73728
    cudaFuncSetAttribute(k_conv, cudaFuncAttributeMaxDynamicSharedMemorySize, DYN_CONV);
    cudaFuncSetAttribute(k_attn, cudaFuncAttributeMaxDynamicSharedMemorySize, DYN_ATTN);

    k_wsplit<<<(KK * DD * DD + 255) / 256, 256>>>(cw);
    k_usplit<<<(LL * DD + 255) / 256, 256>>>(U);
    k_gather<<<(BB * TT * DD + 255) / 256, 256>>>(ids, emb);
    k_conv<<<dim3((TP + 95) / 96, OP2 / 128, BB), 256, DYN_CONV>>>(cb);
    k_attn<<<dim3(LP / 128, BB), 256, DYN_ATTN>>>(fb, out);
}

// round 17
// speedup vs baseline: 1.8693x; 1.1378x over previous
#include <cuda_runtime.h>
#include <cuda_bf16.h>
#include <cuda_fp16.h>
#include <cstdint>
#include <math.h>

typedef unsigned int u32;

// Problem dims
#define BB   8
#define TT   2048
#define DD   300
#define KK   10
#define LL   8921
#define TP   2057     // TT + KK - 1
#define LP   8960     // L padded to 70*128
#define OP2  384      // o padded to 3*128
#define DP   320      // d padded to 20*16
#define TPAD 2176     // t' padded to 17*128 (attn tiling)
#define ETR  2208     // embed rows: 9 halo + 2048 + tail zeros

// Attn stage: A (U hi+lo fp16) 128 rows x 128B = 16KB; B (h hi fp16) 128 rows x 64B = 8KB
#define A_SBB  16384
#define A_STG  24576
// Conv stage: A (W hi+lo fp16) 128 rows x 128B = 16KB; B (E hi fp16) 96 rows x 64B = 6KB
#define C_SBB  16384
#define C_STG  22528
#define NSTG   3

// Scratch (device globals, zero-initialized; padding regions never written)
__device__ __align__(16) __half g_Ehi[BB * ETR * DP];          // [b][9+tau][d] fp16
__device__ __align__(16) __half g_Whi[KK * OP2 * DP];          // [k][o][i] fp16
__device__ __align__(16) __half g_Wlo[KK * OP2 * DP];
__device__ __align__(16) __half g_Uhi[LP * DP];                // [l][d] fp16
__device__ __align__(16) __half g_Ulo[LP * DP];
__device__ __align__(16) __half g_Hthi[BB * TPAD * DP];        // [b][t][o] fp16

// ---------------------------------------------------------------------------
// PTX helpers
// ---------------------------------------------------------------------------
__device__ __forceinline__ u32 smem_u32(const void* p) {
    return (u32)__cvta_generic_to_shared(p);
}

__device__ __forceinline__ void ldsm4(u32* r, u32 addr) {
    asm volatile("ldmatrix.sync.aligned.m8n8.x4.shared.b16 {%0,%1,%2,%3}, [%4];"
                 : "=r"(r[0]), "=r"(r[1]), "=r"(r[2]), "=r"(r[3])
                 : "r"(addr));
}

__device__ __forceinline__ void mma16816h(float* d, const u32* a, const u32* b) {
    asm volatile(
        "mma.sync.aligned.m16n8k16.row.col.f32.f16.f16.f32 "
        "{%0,%1,%2,%3}, {%4,%5,%6,%7}, {%8,%9}, {%0,%1,%2,%3};"
        : "+f"(d[0]), "+f"(d[1]), "+f"(d[2]), "+f"(d[3])
        : "r"(a[0]), "r"(a[1]), "r"(a[2]), "r"(a[3]), "r"(b[0]), "r"(b[1]));
}

__device__ __forceinline__ void cpa16(u32 dst, const void* src) {
    asm volatile("cp.async.cg.shared.global [%0], [%1], 16;" :: "r"(dst), "l"(src));
}
__device__ __forceinline__ void cpa_commit() {
    asm volatile("cp.async.commit_group;");
}
__device__ __forceinline__ void cpa_wait1() {
    asm volatile("cp.async.wait_group 1;");
}
__device__ __forceinline__ void cpa_wait0() {
    asm volatile("cp.async.wait_group 0;");
}

// ---------------------------------------------------------------------------
// Kernel 1: embedding gather -> Ehi[b][9+tau][d] (fp16)
// ---------------------------------------------------------------------------
__global__ void k_gather(const int* __restrict__ ids, const float* __restrict__ emb) {
    int idx = blockIdx.x * 256 + threadIdx.x;
    if (idx >= BB * TT * DD) { return; }
    int d = idx % DD;
    int tok = idx / DD;
    int b = tok / TT;
    int tau = tok - b * TT;
    int row = ids[tok];
    float v = emb[row * DD + d];
    g_Ehi[((size_t)b * ETR + 9 + tau) * DP + d] = __float2half_rn(v);
}

// ---------------------------------------------------------------------------
// Kernel 2: conv_w (O,I,K) fp32 -> fp16 hi/lo split Whi/Wlo[k][o][i]
// ---------------------------------------------------------------------------
__global__ void k_wsplit(const float* __restrict__ w) {
    int idx = blockIdx.x * 256 + threadIdx.x;
    if (idx >= KK * DD * DD) { return; }
    int i = idx % DD;
    int rem = idx / DD;
    int o = rem % DD;
    int k = rem / DD;
    float v = w[(o * DD + i) * KK + k];
    __half h = __float2half_rn(v);
    size_t dst = ((size_t)k * OP2 + o) * DP + i;
    g_Whi[dst] = h;
    g_Wlo[dst] = __float2half_rn(v - __half2float(h));
}

// ---------------------------------------------------------------------------
// Kernel 3: U fp32 [l][d] -> fp16 hi/lo split [l][DP]
// ---------------------------------------------------------------------------
__global__ void k_usplit(const float* __restrict__ U) {
    int idx = blockIdx.x * 256 + threadIdx.x;
    if (idx >= LL * DD) { return; }
    int l = idx / DD;
    int d = idx - l * DD;
    float u = U[idx];
    __half h = __float2half_rn(u);
    g_Uhi[l * DP + d] = h;
    g_Ulo[l * DP + d] = __float2half_rn(u - __half2float(h));
}

// ---------------------------------------------------------------------------
// Conv stage fill: A (W hi/lo, 128 rows x 128B, phys chunk = c^(row&7));
//                  B (E hi, 96 rows x 64B, phys chunk = c^((row>>1)&3))
// ---------------------------------------------------------------------------
__device__ __forceinline__ void stage_fill_c(u32 sb, int tid,
                                             const __half* Ahi,
                                             const __half* Alo,
                                             const __half* Bhi) {
#pragma unroll
    for (int it = 0; it < 4; it++) {
        int idx = tid + it * 256;
        int row = idx >> 3;
        int c = idx & 7;
        u32 dst = sb + (u32)(row * 128) + (u32)(((c ^ (row & 7)) << 4));
        size_t go = (size_t)row * DP + (c & 3) * 8;
        cpa16(dst, (c < 4) ? (Ahi + go) : (Alo + go));
    }
#pragma unroll
    for (int it = 0; it < 2; it++) {
        int idx = tid + it * 256;
        if (idx < 384) {
            int row = idx >> 2;
            int c = idx & 3;
            u32 dst = sb + (u32)C_SBB + (u32)(row * 64)
                    + (u32)(((c ^ ((row >> 1) & 3)) << 4));
            size_t go = (size_t)row * DP + c * 8;
            cpa16(dst, Bhi + go);
        }
    }
    cpa_commit();
}

// ---------------------------------------------------------------------------
// Attn stage fill: A (U hi/lo, 128 rows x 128B); B (h hi, 128 rows x 64B)
// ---------------------------------------------------------------------------
__device__ __forceinline__ void stage_fill_a(u32 sb, int tid,
                                             const __half* Ahi,
                                             const __half* Alo,
                                             const __half* Bhi) {
#pragma unroll
    for (int it = 0; it < 4; it++) {
        int idx = tid + it * 256;
        int row = idx >> 3;
        int c = idx & 7;
        u32 dst = sb + (u32)(row * 128) + (u32)(((c ^ (row & 7)) << 4));
        size_t go = (size_t)row * DP + (c & 3) * 8;
        cpa16(dst, (c < 4) ? (Ahi + go) : (Alo + go));
    }
#pragma unroll
    for (int it = 0; it < 2; it++) {
        int idx = tid + it * 256;
        int row = idx >> 2;
        int c = idx & 3;
        u32 dst = sb + (u32)A_SBB + (u32)(row * 64)
                + (u32)(((c ^ ((row >> 1) & 3)) << 4));
        size_t go = (size_t)row * DP + c * 8;
        cpa16(dst, Bhi + go);
    }
    cpa_commit();
}

// ---------------------------------------------------------------------------
// Conv mma phase: fp16 2-pass (W_hi*E + W_lo*E), warp tile 32x48
// ---------------------------------------------------------------------------
__device__ __forceinline__ void mma_phase_c(u32 sb, const u32* rA, const u32* rB,
                                            u32 xa, u32 c0a, u32 xb, u32 c0b,
                                            float acc[2][6][4]) {
#pragma unroll
    for (int kc = 0; kc < 2; kc++) {
        u32 ca = c0a + (u32)(kc * 2);
        u32 cb = c0b + (u32)(kc * 2);
        u32 ah0[4];
        u32 ah1[4];
        u32 al0[4];
        u32 al1[4];
        u32 bh[3][4];

        ldsm4(ah0, sb + rA[0] + ((ca ^ xa) << 4));
        ldsm4(ah1, sb + rA[1] + ((ca ^ xa) << 4));
#pragma unroll
        for (int j2 = 0; j2 < 3; j2++) {
            ldsm4(bh[j2], sb + rB[j2] + ((cb ^ xb) << 4));
        }

        // pass 1: W_hi * E
#pragma unroll
        for (int j = 0; j < 6; j++) {
            const u32* bp = &bh[j >> 1][(j & 1) * 2];
            mma16816h(acc[0][j], ah0, bp);
            mma16816h(acc[1][j], ah1, bp);
        }

        // pass 2: W_lo * E
        ldsm4(al0, sb + rA[0] + (((ca + 4) ^ xa) << 4));
        ldsm4(al1, sb + rA[1] + (((ca + 4) ^ xa) << 4));
#pragma unroll
        for (int j = 0; j < 6; j++) {
            const u32* bp = &bh[j >> 1][(j & 1) * 2];
            mma16816h(acc[0][j], al0, bp);
            mma16816h(acc[1][j], al1, bp);
        }
    }
}

// ---------------------------------------------------------------------------
// Attn mma phase: fp16 2-pass (U_hi*h + U_lo*h), warp tile 32x64
// ---------------------------------------------------------------------------
__device__ __forceinline__ void mma_phase_a(u32 sb, const u32* rA, const u32* rB,
                                            u32 xa, u32 c0a, u32 xb, u32 c0b,
                                            float acc[2][8][4]) {
#pragma unroll
    for (int kc = 0; kc < 2; kc++) {
        u32 ca = c0a + (u32)(kc * 2);
        u32 cb = c0b + (u32)(kc * 2);
        u32 ah0[4];
        u32 ah1[4];
        u32 al0[4];
        u32 al1[4];
        u32 bh[4][4];

        ldsm4(ah0, sb + rA[0] + ((ca ^ xa) << 4));
        ldsm4(ah1, sb + rA[1] + ((ca ^ xa) << 4));
#pragma unroll
        for (int j2 = 0; j2 < 4; j2++) {
            ldsm4(bh[j2], sb + rB[j2] + ((cb ^ xb) << 4));
        }

#pragma unroll
        for (int j = 0; j < 8; j++) {
            const u32* bp = &bh[j >> 1][(j & 1) * 2];
            mma16816h(acc[0][j], ah0, bp);
            mma16816h(acc[1][j], ah1, bp);
        }

        ldsm4(al0, sb + rA[0] + (((ca + 4) ^ xa) << 4));
        ldsm4(al1, sb + rA[1] + (((ca + 4) ^ xa) << 4));
#pragma unroll
        for (int j = 0; j < 8; j++) {
            const u32* bp = &bh[j >> 1][(j & 1) * 2];
            mma16816h(acc[0][j], al0, bp);
            mma16816h(acc[1][j], al1, bp);
        }
    }
}

// ---------------------------------------------------------------------------
// Kernel 4: conv1d, block 128o x 96t (8 warps, 32x48 tiles), fp16 2-pass,
//           3-stage pipeline, 100 phases (k x d-chunk)
// ---------------------------------------------------------------------------
__global__ void __launch_bounds__(256, 2) k_conv(const float* __restrict__ conv_b) {
    extern __shared__ __align__(16) char dynsm[];
    int t0 = blockIdx.x * 96;
    int o0 = blockIdx.y * 128;
    int b  = blockIdx.z;
    int tid = threadIdx.x;
    int lane = tid & 31;
    int warp = tid >> 5;
    int warp_m = warp >> 1;
    int warp_n = warp & 1;
    int g = lane >> 2;
    int q = lane & 3;

    u32 smbase = smem_u32(dynsm);
    u32 xa = (u32)(lane & 7);
    u32 c0a = (u32)(lane >> 4);
    u32 xb = (u32)((lane >> 1) & 3);
    u32 c0b = (u32)((lane >> 3) & 1);

    u32 rA[2];
#pragma unroll
    for (int mt = 0; mt < 2; mt++) {
        rA[mt] = (u32)((warp_m * 32 + mt * 16 + (lane & 15)) * 128);
    }
    u32 rB[3];
    {
        int brow = ((lane >> 4) & 1) * 8 + (lane & 7);
#pragma unroll
        for (int j2 = 0; j2 < 3; j2++) {
            rB[j2] = (u32)(C_SBB + (warp_n * 48 + j2 * 16 + brow) * 64);
        }
    }

    float acc[2][6][4];
#pragma unroll
    for (int mt = 0; mt < 2; mt++) {
#pragma unroll
        for (int j = 0; j < 6; j++) {
#pragma unroll
            for (int c = 0; c < 4; c++) { acc[mt][j][c] = 0.f; }
        }
    }

    const int NPH = 100;

#pragma unroll 1
    for (int pre = 0; pre < 2; pre++) {
        int k = pre / 10;
        int d0 = (pre % 10) * 32;
        stage_fill_c(smbase + (u32)(pre * C_STG), tid,
                     g_Whi + ((size_t)k * OP2 + o0) * DP + d0,
                     g_Wlo + ((size_t)k * OP2 + o0) * DP + d0,
                     g_Ehi + ((size_t)b * ETR + t0 + k) * DP + d0);
    }

    int slot = 0;
    int islot = 2;
#pragma unroll 1
    for (int p = 0; p < NPH; p++) {
        if (p < NPH - 1) { cpa_wait1(); } else { cpa_wait0(); }
        __syncthreads();

        if (p + 2 < NPH) {
            int pn = p + 2;
            int k = pn / 10;
            int d0 = (pn - k * 10) * 32;
            stage_fill_c(smbase + (u32)(islot * C_STG), tid,
                         g_Whi + ((size_t)k * OP2 + o0) * DP + d0,
                         g_Wlo + ((size_t)k * OP2 + o0) * DP + d0,
                         g_Ehi + ((size_t)b * ETR + t0 + k) * DP + d0);
        }

        mma_phase_c(smbase + (u32)(slot * C_STG), rA, rB, xa, c0a, xb, c0b, acc);

        slot++;
        if (slot == NSTG) { slot = 0; }
        islot++;
        if (islot == NSTG) { islot = 0; }
    }

    // Epilogue: bias + relu, fp16 store transposed to [t][o]
#pragma unroll
    for (int mt = 0; mt < 2; mt++) {
#pragma unroll
        for (int ch = 0; ch < 2; ch++) {
            int o = o0 + warp_m * 32 + mt * 16 + g + ch * 8;
            if (o < DD) {
                float bias = conv_b[o];
#pragma unroll
                for (int j = 0; j < 6; j++) {
#pragma unroll
                    for (int bb2 = 0; bb2 < 2; bb2++) {
                        int t = t0 + warp_n * 48 + j * 8 + q * 2 + bb2;
                        if (t < TP) {
                            float v = fmaxf(acc[mt][j][ch * 2 + bb2] + bias, 0.f);
                            size_t dst = ((size_t)b * TPAD + t) * DP + o;
                            g_Hthi[dst] = __float2half_rn(v);
                        }
                    }
                }
            }
        }
    }
}

// ---------------------------------------------------------------------------
// Kernel 5: fused score-GEMM (fp16 2-pass) + online softmax, 3-stage pipeline
//   block: 128 l x 128 t-tile, 8 warps (4m x 2n, 32x64), 170 phases
// ---------------------------------------------------------------------------
__global__ void __launch_bounds__(256, 2) k_attn(const float* __restrict__ fc_bias,
                                                 float* __restrict__ out) {
    extern __shared__ __align__(16) char dynsm[];
    __shared__ float s_m[128];
    __shared__ float s_e[128];
    __shared__ float s_s[128];
    __shared__ float p_m[2][128];
    __shared__ float p_e[2][128];
    __shared__ float p_s[2][128];

    int l0 = blockIdx.x * 128;
    int b  = blockIdx.y;
    int tid = threadIdx.x;
    int lane = tid & 31;
    int warp = tid >> 5;
    int warp_m = warp >> 1;
    int warp_n = warp & 1;
    int g = lane >> 2;
    int q = lane & 3;

    if (tid < 128) {
        s_m[tid] = -INFINITY;
        s_e[tid] = 0.f;
        s_s[tid] = 0.f;
    }

    u32 smbase = smem_u32(dynsm);
    u32 xa = (u32)(lane & 7);
    u32 c0a = (u32)(lane >> 4);
    u32 xb = (u32)((lane >> 1) & 3);
    u32 c0b = (u32)((lane >> 3) & 1);

    u32 rA[2];
#pragma unroll
    for (int mt = 0; mt < 2; mt++) {
        rA[mt] = (u32)((warp_m * 32 + mt * 16 + (lane & 15)) * 128);
    }
    u32 rB[4];
    {
        int brow = ((lane >> 4) & 1) * 8 + (lane & 7);
#pragma unroll
        for (int j2 = 0; j2 < 4; j2++) {
            rB[j2] = (u32)(A_SBB + (warp_n * 64 + j2 * 16 + brow) * 64);
        }
    }

    const __half* BHbase = g_Hthi + (size_t)b * TPAD * DP;

    const int NPH = 170;

#pragma unroll 1
    for (int pre = 0; pre < 2; pre++) {
        int d0 = (pre % 10) * 32;
        stage_fill_a(smbase + (u32)(pre * A_STG), tid,
                     g_Uhi + (size_t)l0 * DP + d0,
                     g_Ulo + (size_t)l0 * DP + d0,
                     BHbase + d0);
    }

    float acc[2][8][4];
    int slot = 0;
    int islot = 2;

#pragma unroll 1
    for (int p = 0; p < NPH; p++) {
        int tile = p / 10;
        int ph = p - tile * 10;

        if (ph == 0) {
#pragma unroll
            for (int mt = 0; mt < 2; mt++) {
#pragma unroll
                for (int j = 0; j < 8; j++) {
#pragma unroll
                    for (int c = 0; c < 4; c++) { acc[mt][j][c] = 0.f; }
                }
            }
        }

        if (p < NPH - 1) { cpa_wait1(); } else { cpa_wait0(); }
        __syncthreads();

        if (p + 2 < NPH) {
            int pn = p + 2;
            int tn = pn / 10;
            int d0 = (pn - tn * 10) * 32;
            int tt0 = tn * 128;
            stage_fill_a(smbase + (u32)(islot * A_STG), tid,
                         g_Uhi + (size_t)l0 * DP + d0,
                         g_Ulo + (size_t)l0 * DP + d0,
                         BHbase + (size_t)tt0 * DP + d0);
        }

        mma_phase_a(smbase + (u32)(slot * A_STG), rA, rB, xa, c0a, xb, c0b, acc);

        if (ph == 9) {
            int t0 = tile * 128;
#pragma unroll
            for (int mt = 0; mt < 2; mt++) {
#pragma unroll
                for (int ch = 0; ch < 2; ch++) {
                    int row = warp_m * 32 + mt * 16 + g + ch * 8;
                    float mx = -INFINITY;
                    float pe = 0.f;
                    float ps = 0.f;
                    if (tile < 16) {
                        // fast path: all 128 t-cols valid
#pragma unroll
                        for (int j = 0; j < 8; j++) {
#pragma unroll
                            for (int bb2 = 0; bb2 < 2; bb2++) {
                                mx = fmaxf(mx, acc[mt][j][ch * 2 + bb2]);
                            }
                        }
                        mx = fmaxf(mx, __shfl_xor_sync(0xffffffffu, mx, 1));
                        mx = fmaxf(mx, __shfl_xor_sync(0xffffffffu, mx, 2));
#pragma unroll
                        for (int j = 0; j < 8; j++) {
#pragma unroll
                            for (int bb2 = 0; bb2 < 2; bb2++) {
                                float v = acc[mt][j][ch * 2 + bb2];
                                float pv = __expf(v - mx);
                                pe += pv;
                                ps += pv * v;
                            }
                        }
                    } else {
                        // masked tail tile (t0 = 2048, valid t < 2057)
#pragma unroll
                        for (int j = 0; j < 8; j++) {
#pragma unroll
                            for (int bb2 = 0; bb2 < 2; bb2++) {
                                int t = t0 + warp_n * 64 + j * 8 + q * 2 + bb2;
                                if (t < TP) { mx = fmaxf(mx, acc[mt][j][ch * 2 + bb2]); }
                            }
                        }
                        mx = fmaxf(mx, __shfl_xor_sync(0xffffffffu, mx, 1));
                        mx = fmaxf(mx, __shfl_xor_sync(0xffffffffu, mx, 2));
#pragma unroll
                        for (int j = 0; j < 8; j++) {
#pragma unroll
                            for (int bb2 = 0; bb2 < 2; bb2++) {
                                int t = t0 + warp_n * 64 + j * 8 + q * 2 + bb2;
                                if (t < TP) {
                                    float v = acc[mt][j][ch * 2 + bb2];
                                    float pv = __expf(v - mx);
                                    pe += pv;
                                    ps += pv * v;
                                }
                            }
                        }
                    }
                    pe += __shfl_xor_sync(0xffffffffu, pe, 1);
                    ps += __shfl_xor_sync(0xffffffffu, ps, 1);
                    pe += __shfl_xor_sync(0xffffffffu, pe, 2);
                    ps += __shfl_xor_sync(0xffffffffu, ps, 2);

                    if (q == 0) {
                        p_m[warp_n][row] = mx;
                        p_e[warp_n][row] = pe;
                        p_s[warp_n][row] = ps;
                    }
                }
            }
            __syncthreads();

            if (tid < 128) {
                float mo = s_m[tid];
                float eo = s_e[tid];
                float so = s_s[tid];
#pragma unroll
                for (int pp = 0; pp < 2; pp++) {
                    float mxp = p_m[pp][tid];
                    float pep = p_e[pp][tid];
                    float psp = p_s[pp][tid];
                    float mn = fmaxf(mo, mxp);
                    float e1 = __expf(mo - mn);
                    float e2 = __expf(mxp - mn);
                    eo = eo * e1 + pep * e2;
                    so = so * e1 + psp * e2;
                    mo = mn;
                }
                s_m[tid] = mo;
                s_e[tid] = eo;
                s_s[tid] = so;
            }
        }

        slot++;
        if (slot == NSTG) { slot = 0; }
        islot++;
        if (islot == NSTG) { islot = 0; }
    }

    if (tid < 128) {
        int l = l0 + tid;
        if (l < LL) { out[b * LL + l] = s_s[tid] / s_e[tid] + fc_bias[l]; }
    }
}

// ---------------------------------------------------------------------------
// Launch
// ---------------------------------------------------------------------------
extern "C" void kernel_launch(void* const* d_in, const int* in_sizes, int n_in,
                              void* d_out, int out_size) {
    const int* ids = nullptr;
    const float* emb = nullptr;
    const float* cw = nullptr;
    const float* cb = nullptr;
    const float* U = nullptr;
    const float* fb = nullptr;
    for (int i = 0; i < n_in; i++) {
        int s = in_sizes[i];
        if (s == BB * TT) { ids = (const int*)d_in[i]; }
        else if (s == 50000 * DD) { emb = (const float*)d_in[i]; }
        else if (s == DD * DD * KK) { cw = (const float*)d_in[i]; }
        else if (s == DD) { cb = (const float*)d_in[i]; }
        else if (s == LL * DD) { U = (const float*)d_in[i]; }
        else if (s == LL) { fb = (const float*)d_in[i]; }
    }
    float* out = (float*)d_out;

    const int DYN_CONV = NSTG * C_STG;   // 67584
    const int DYN_ATTN = NSTG * A_STG;   // 73728
    cudaFuncSetAttribute(k_conv, cudaFuncAttributeMaxDynamicSharedMemorySize, DYN_CONV);
    cudaFuncSetAttribute(k_attn, cudaFuncAttributeMaxDynamicSharedMemorySize, DYN_ATTN);

    k_wsplit<<<(KK * DD * DD + 255) / 256, 256>>>(cw);
    k_usplit<<<(LL * DD + 255) / 256, 256>>>(U);
    k_gather<<<(BB * TT * DD + 255) / 256, 256>>>(ids, emb);
    k_conv<<<dim3((TP + 95) / 96, OP2 / 128, BB), 256, DYN_CONV>>>(cb);
    k_attn<<<dim3(LP / 128, BB), 256, DYN_ATTN>>>(fb, out);
}